// round 2
// baseline (speedup 1.0000x reference)
#include <cuda_runtime.h>

#define NN 50000
#define NE 600000
#define HH 128
#define LL 6

typedef unsigned long long u64;

// ---------------- scratch (static device buffers; no allocation) ----------------
__device__ float g_h  [NN*HH];
__device__ float g_hn [NN*HH];
__device__ float g_up [NN*HH];
__device__ float g_agg[NN*HH];
__device__ float g_m1 [(size_t)NE*HH];
__device__ float g_tail[NE*4];
__device__ float g_deg[NN];
__device__ float g_invdeg[NN];
__device__ float g_var[NN];
__device__ float g_sum[HH];
__device__ float g_sumsq[HH];
__device__ float g_ba[HH];
__device__ float g_bc[HH];

// ---------------- packed f32x2 helpers (Blackwell FFMA2) ----------------
__device__ __forceinline__ void fma2(u64 &d, u64 a, u64 b){
    asm("fma.rn.f32x2 %0, %1, %2, %0;" : "+l"(d) : "l"(a), "l"(b));
}
__device__ __forceinline__ u64 pk2(float x, float y){
    u64 r; asm("mov.b64 %0, {%1, %2};" : "=l"(r) : "f"(x), "f"(y)); return r;
}
__device__ __forceinline__ float2 upk2(u64 v){
    float2 r; asm("mov.b64 {%0, %1}, %2;" : "=f"(r.x), "=f"(r.y) : "l"(v)); return r;
}

#define EPI_RELU_STORE 0
#define EPI_ATOMIC     1
#define EPI_RESID      2
#define EPI_STORE      3

// AMODE: 0 = A is dense rows x 128
//        1 = message gather: [h[dst] | h[src] | tail(du,dpx,dpy,var_i)]  K=260
//        2 = update gather:  [h[n] | agg[n]/deg[n] | var[n]]            K=257
template<int AMODE, int EPI>
__global__ __launch_bounds__(256)
void gemm_k(const float* __restrict__ A, const float* __restrict__ W,
            const float* __restrict__ bias, float* __restrict__ out,
            const int* __restrict__ esrc, const int* __restrict__ edst,
            int rows, int K)
{
    __shared__ float As[16][68];     // [k][m], padded stride vs bank conflicts
    __shared__ float Bs[16][128];    // [k][j]
    __shared__ int   s_ia[64];
    __shared__ int   s_ib[64];
    __shared__ float s_fa[64];
    __shared__ float s_fb[64];

    const int tid  = threadIdx.x;
    const int base = blockIdx.x * 64;

    if (tid < 64) {
        int r = base + tid; if (r >= rows) r = rows - 1;
        if (AMODE == 1)        { s_ia[tid] = edst[r]; s_ib[tid] = esrc[r]; }
        else if (AMODE == 2)   { s_fa[tid] = g_invdeg[r]; s_fb[tid] = g_var[r]; }
        if (EPI == EPI_ATOMIC) { s_ia[tid] = edst[r]; }
    }
    __syncthreads();

    const int lm  = tid >> 2;         // A tile row 0..63
    const int lc  = (tid & 3) * 4;    // A tile k offset 0/4/8/12
    const int bk  = tid >> 5;         // B tile k row 0..7
    const int bj  = (tid & 31) * 4;   // B tile col
    const int ty  = tid >> 5;         // output row group 0..7
    const int txc = (tid & 31) * 4;   // output cols

    int arow = base + lm; if (arow >= rows) arow = rows - 1;

    u64 acc[4][4];
    #pragma unroll
    for (int i=0;i<4;i++)
        #pragma unroll
        for (int j=0;j<4;j++) acc[i][j]=0ULL;

    const int nkt = (K + 15) >> 4;
    for (int kt = 0; kt < nkt; kt++) {
        // ---- gather A fragment (one float4 per thread) ----
        float4 av = make_float4(0.f,0.f,0.f,0.f);
        int k0 = kt*16 + lc;
        if (AMODE == 0) {
            av = *(const float4*)&A[arow*128 + k0];
        } else if (AMODE == 1) {
            if (k0 < 128)       av = *(const float4*)&g_h[s_ia[lm]*HH + k0];
            else if (k0 < 256)  av = *(const float4*)&g_h[s_ib[lm]*HH + (k0-128)];
            else if (k0 == 256) av = *(const float4*)&g_tail[arow*4];
        } else {
            if (k0 < 128)       av = *(const float4*)&g_h[arow*HH + k0];
            else if (k0 < 256)  { av = *(const float4*)&g_agg[arow*HH + (k0-128)];
                                  float s = s_fa[lm];
                                  av.x*=s; av.y*=s; av.z*=s; av.w*=s; }
            else if (k0 == 256) av = make_float4(s_fb[lm],0.f,0.f,0.f);
        }
        // ---- B fragment (two float4 per thread) ----
        float4 bv0 = make_float4(0.f,0.f,0.f,0.f), bv1 = bv0;
        int kg0 = kt*16 + bk, kg1 = kg0 + 8;
        if (kg0 < K) bv0 = *(const float4*)&W[kg0*128 + bj];
        if (kg1 < K) bv1 = *(const float4*)&W[kg1*128 + bj];

        // previous compute finished at loop-bottom sync
        As[lc+0][lm]=av.x; As[lc+1][lm]=av.y; As[lc+2][lm]=av.z; As[lc+3][lm]=av.w;
        *(float4*)&Bs[bk  ][bj] = bv0;
        *(float4*)&Bs[bk+8][bj] = bv1;
        __syncthreads();

        #pragma unroll
        for (int k=0;k<16;k++){
            union { float4 f; u64 u[2]; } ua0, ua1, ub;
            ua0.f = *(const float4*)&As[k][ty*8];
            ua1.f = *(const float4*)&As[k][ty*8+4];
            ub.f  = *(const float4*)&Bs[k][txc];
            u64 ap[4] = { ua0.u[0], ua0.u[1], ua1.u[0], ua1.u[1] };  // row pairs, packed for free
            u64 bp[4] = { pk2(ub.f.x,ub.f.x), pk2(ub.f.y,ub.f.y),
                          pk2(ub.f.z,ub.f.z), pk2(ub.f.w,ub.f.w) };
            #pragma unroll
            for (int i=0;i<4;i++)
                #pragma unroll
                for (int j=0;j<4;j++)
                    fma2(acc[i][j], ap[i], bp[j]);
        }
        __syncthreads();
    }

    // ---- epilogue ----
    float4 bb = *(const float4*)&bias[txc];
    #pragma unroll
    for (int i=0;i<4;i++){
        float2 c0 = upk2(acc[i][0]);
        float2 c1 = upk2(acc[i][1]);
        float2 c2 = upk2(acc[i][2]);
        float2 c3 = upk2(acc[i][3]);
        #pragma unroll
        for (int sub=0; sub<2; sub++){
            int lrow = ty*8 + i*2 + sub;
            int r = base + lrow;
            if (r >= rows) continue;
            float v0 = (sub? c0.y : c0.x) + bb.x;
            float v1 = (sub? c1.y : c1.x) + bb.y;
            float v2 = (sub? c2.y : c2.x) + bb.z;
            float v3 = (sub? c3.y : c3.x) + bb.w;
            if (EPI != EPI_STORE){
                v0=fmaxf(v0,0.f); v1=fmaxf(v1,0.f); v2=fmaxf(v2,0.f); v3=fmaxf(v3,0.f);
            }
            if (EPI == EPI_ATOMIC){
                int n = s_ia[lrow];
                atomicAdd(&out[n*HH+txc+0], v0);
                atomicAdd(&out[n*HH+txc+1], v1);
                atomicAdd(&out[n*HH+txc+2], v2);
                atomicAdd(&out[n*HH+txc+3], v3);
            } else if (EPI == EPI_RESID){
                float4 hv = *(const float4*)&g_h[r*HH+txc];
                *(float4*)&out[r*HH+txc] =
                    make_float4(hv.x+v0, hv.y+v1, hv.z+v2, hv.w+v3);
            } else {
                *(float4*)&out[r*HH+txc] = make_float4(v0,v1,v2,v3);
            }
        }
    }
}

// ---------------- small kernels ----------------
__global__ void k_zero(float* __restrict__ p, int n){
    int i = blockIdx.x*blockDim.x + threadIdx.x;
    if (i < n) p[i] = 0.f;
}

__global__ void k_node_pre(const float* __restrict__ pos){
    int n = blockIdx.x*blockDim.x + threadIdx.x;
    if (n < NN){ g_var[n] = pos[n*3+0]; g_deg[n] = 0.f; }
}

__global__ void k_edge_pre(const float* __restrict__ u, const float* __restrict__ pos,
                           const int* __restrict__ src, const int* __restrict__ dst){
    int e = blockIdx.x*blockDim.x + threadIdx.x;
    if (e < NE){
        int s = src[e], d = dst[e];
        g_tail[e*4+0] = u[d] - u[s];
        g_tail[e*4+1] = pos[d*3+1] - pos[s*3+1];
        g_tail[e*4+2] = pos[d*3+2] - pos[s*3+2];
        g_tail[e*4+3] = pos[d*3+0];
        atomicAdd(&g_deg[d], 1.f);
    }
}

__global__ void k_invdeg(){
    int n = blockIdx.x*blockDim.x + threadIdx.x;
    if (n < NN) g_invdeg[n] = 1.f / fmaxf(g_deg[n], 1.f);
}

__global__ void k_h0(const float* __restrict__ u, const float* __restrict__ pos,
                     const float* __restrict__ W1, const float* __restrict__ b1){
    int idx = blockIdx.x*blockDim.x + threadIdx.x;
    if (idx < NN*HH){
        int n = idx >> 7, j = idx & 127;
        float val = u[n]        * W1[j]
                  + pos[n*3+1]  * W1[128+j]
                  + pos[n*3+2]  * W1[256+j]
                  + pos[n*3+0]  * W1[384+j]
                  + b1[j];
        g_hn[idx] = val;
    }
}

__global__ void k_bn_zero(){
    int t = threadIdx.x;
    if (t < HH){ g_sum[t]=0.f; g_sumsq[t]=0.f; }
}

__global__ void k_bn_stats(const float* __restrict__ x){
    int j = threadIdx.x;
    int r0 = blockIdx.x * 256;
    int rend = min(r0 + 256, NN);
    float s = 0.f, s2 = 0.f;
    for (int r = r0; r < rend; r++){
        float v = x[r*HH + j];
        s += v; s2 += v*v;
    }
    atomicAdd(&g_sum[j], s);
    atomicAdd(&g_sumsq[j], s2);
}

__global__ void k_bn_fin(const float* __restrict__ g, const float* __restrict__ be){
    int j = threadIdx.x;
    float mu  = g_sum[j]   * (1.f/NN);
    float var = g_sumsq[j] * (1.f/NN) - mu*mu;
    float a = g[j] * rsqrtf(var + 1e-5f);
    g_ba[j] = a;
    g_bc[j] = be[j] - a*mu;
}

template<bool RELU>
__global__ void k_bn_apply(const float* __restrict__ x, float* __restrict__ y){
    int i4 = blockIdx.x*blockDim.x + threadIdx.x;
    if (i4 < NN*HH/4){
        int j = (i4*4) & 127;
        float4 v = *(const float4*)&x[i4*4];
        float4 a = *(const float4*)&g_ba[j];
        float4 c = *(const float4*)&g_bc[j];
        float4 o = make_float4(a.x*v.x+c.x, a.y*v.y+c.y, a.z*v.z+c.z, a.w*v.w+c.w);
        if (RELU){
            o.x=fmaxf(o.x,0.f); o.y=fmaxf(o.y,0.f);
            o.z=fmaxf(o.z,0.f); o.w=fmaxf(o.w,0.f);
        }
        *(float4*)&y[i4*4] = o;
    }
}

// ---------------- CNN head: per-node tiny convs ----------------
__global__ __launch_bounds__(64)
void k_cnn(const float* __restrict__ c1W, const float* __restrict__ c1b,
           const float* __restrict__ c2W, const float* __restrict__ c2b,
           const float* __restrict__ c3W, const float* __restrict__ c3b,
           float* __restrict__ out){
    __shared__ float sx[64][129];
    __shared__ float w1[64], w2[384], w3[64], b1[4], b2[8], b3[1];
    int tid = threadIdx.x;
    int base = blockIdx.x * 64;

    w1[tid] = c1W[tid];
    w3[tid] = c3W[tid];
    for (int i = tid; i < 384; i += 64) w2[i] = c2W[i];
    if (tid < 4) b1[tid] = c1b[tid];
    if (tid < 8) b2[tid] = c2b[tid];
    if (tid == 0) b3[0] = c3b[0];

    for (int r = 0; r < 64; r++){
        int row = base + r; int rr = row < NN ? row : NN-1;
        sx[r][tid]    = g_h[rr*HH + tid];
        sx[r][tid+64] = g_h[rr*HH + tid + 64];
    }
    __syncthreads();

    int node = base + tid;
    if (node >= NN) return;

    float o1[4][38];
    #pragma unroll
    for (int c = 0; c < 4; c++)
        for (int p = 0; p < 38; p++){
            float s = b1[c];
            #pragma unroll
            for (int k = 0; k < 16; k++) s += sx[tid][3*p+k] * w1[c*16+k];
            o1[c][p] = fmaxf(s, 0.f);
        }
    float o2[8][9];
    for (int o = 0; o < 8; o++)
        for (int q = 0; q < 9; q++){
            float s = b2[o];
            for (int c = 0; c < 4; c++)
                #pragma unroll
                for (int k = 0; k < 12; k++) s += o1[c][3*q+k] * w2[(o*4+c)*12+k];
            o2[o][q] = fmaxf(s, 0.f);
        }
    float s = b3[0];
    #pragma unroll
    for (int o = 0; o < 8; o++)
        #pragma unroll
        for (int k = 0; k < 8; k++) s += o2[o][k] * w3[o*8+k];

    out[node] = 0.001f * s;   // dt = cumsum(DT*0.1) with TW=1
}

// ---------------- launch ----------------
extern "C" void kernel_launch(void* const* d_in, const int* in_sizes, int n_in,
                              void* d_out, int out_size)
{
    const float* u      = (const float*)d_in[0];
    const float* pos    = (const float*)d_in[1];
    const int*   ei     = (const int*)  d_in[2];
    const int*   src    = ei;
    const int*   dst    = ei + NE;
    const float* emb_W1 = (const float*)d_in[3];
    const float* emb_b1 = (const float*)d_in[4];
    const float* emb_g1 = (const float*)d_in[5];
    const float* emb_be1= (const float*)d_in[6];
    const float* emb_W2 = (const float*)d_in[7];
    const float* emb_b2 = (const float*)d_in[8];
    const float* emb_g2 = (const float*)d_in[9];
    const float* emb_be2= (const float*)d_in[10];
    const float* m1W    = (const float*)d_in[11];
    const float* m1b    = (const float*)d_in[12];
    const float* m2W    = (const float*)d_in[13];
    const float* m2b    = (const float*)d_in[14];
    const float* u1W    = (const float*)d_in[15];
    const float* u1b    = (const float*)d_in[16];
    const float* u2W    = (const float*)d_in[17];
    const float* u2b    = (const float*)d_in[18];
    const float* bng    = (const float*)d_in[19];
    const float* bnb    = (const float*)d_in[20];
    const float* c1W    = (const float*)d_in[21];
    const float* c1b    = (const float*)d_in[22];
    const float* c2W    = (const float*)d_in[23];
    const float* c2b    = (const float*)d_in[24];
    const float* c3W    = (const float*)d_in[25];
    const float* c3b    = (const float*)d_in[26];
    float* out = (float*)d_out;

    float *p_h, *p_hn, *p_up, *p_agg, *p_m1;
    cudaGetSymbolAddress((void**)&p_h,   g_h);
    cudaGetSymbolAddress((void**)&p_hn,  g_hn);
    cudaGetSymbolAddress((void**)&p_up,  g_up);
    cudaGetSymbolAddress((void**)&p_agg, g_agg);
    cudaGetSymbolAddress((void**)&p_m1,  g_m1);

    const int GN  = (NN + 63) / 64;      // node-row GEMM blocks
    const int GE  = NE / 64;             // edge-row GEMM blocks (exact)
    const int ELT = (NN*HH + 255) / 256;

    auto bn = [&](const float* x, float* y, const float* g, const float* be, bool relu){
        k_bn_zero<<<1,128>>>();
        k_bn_stats<<<(NN+255)/256,128>>>(x);
        k_bn_fin<<<1,128>>>(g, be);
        if (relu) k_bn_apply<true ><<<(NN*HH/4+255)/256,256>>>(x, y);
        else      k_bn_apply<false><<<(NN*HH/4+255)/256,256>>>(x, y);
    };

    // preprocessing
    k_node_pre<<<(NN+255)/256,256>>>(pos);
    k_edge_pre<<<(NE+255)/256,256>>>(u, pos, src, dst);
    k_invdeg<<<(NN+255)/256,256>>>();

    // embedding
    k_h0<<<(NN*HH+255)/256,256>>>(u, pos, emb_W1, emb_b1);
    bn(p_hn, p_h, emb_g1, emb_be1, true);
    gemm_k<0,EPI_STORE><<<GN,256>>>(p_h, emb_W2, emb_b2, p_hn,
                                    nullptr, nullptr, NN, 128);
    bn(p_hn, p_h, emb_g2, emb_be2, false);

    // message-passing layers
    for (int i = 0; i < LL; i++){
        gemm_k<1,EPI_RELU_STORE><<<GE,256>>>(nullptr, m1W + (size_t)i*260*128,
                                             m1b + i*128, p_m1, src, dst, NE, 260);
        k_zero<<<ELT,256>>>(p_agg, NN*HH);
        gemm_k<0,EPI_ATOMIC><<<GE,256>>>(p_m1, m2W + (size_t)i*128*128,
                                         m2b + i*128, p_agg, nullptr, dst, NE, 128);
        gemm_k<2,EPI_RELU_STORE><<<GN,256>>>(nullptr, u1W + (size_t)i*257*128,
                                             u1b + i*128, p_up, nullptr, nullptr, NN, 257);
        gemm_k<0,EPI_RESID><<<GN,256>>>(p_up, u2W + (size_t)i*128*128,
                                        u2b + i*128, p_hn, nullptr, nullptr, NN, 128);
        bn(p_hn, p_h, bng + i*128, bnb + i*128, false);
    }

    // CNN head
    k_cnn<<<GN,64>>>(c1W, c1b, c2W, c2b, c3W, c3b, out);
}

// round 3
// speedup vs baseline: 2.2058x; 2.2058x over previous
#include <cuda_runtime.h>

#define NN 50000
#define NE 600000
#define HH 128
#define LL 6

typedef unsigned long long u64;

// ---------------- scratch (static device buffers; no allocation) ----------------
__device__ float g_h  [NN*HH];
__device__ float g_hn [NN*HH];
__device__ float g_up [NN*HH];
__device__ float g_agg[NN*HH];
__device__ float g_Pd [NN*HH];
__device__ float g_Ps [NN*HH];
__device__ float4 g_tl[NE];          // sorted edge tails (du,dpx,dpy,var)
__device__ int   g_sdst[NE];
__device__ int   g_ssrc[NE];
__device__ int   g_cnt[NN];
__device__ int   g_woff[NN];
__device__ float g_invdeg[NN];
__device__ float g_var[NN];
__device__ float g_sum[HH];
__device__ float g_sumsq[HH];
__device__ float g_ba[HH];
__device__ float g_bc[HH];
__device__ float g_zero[HH];         // stays zero (zero-initialized, never written)

// ---------------- packed f32x2 helpers (Blackwell FFMA2) ----------------
__device__ __forceinline__ void fma2(u64 &d, u64 a, u64 b){
    asm("fma.rn.f32x2 %0, %1, %2, %0;" : "+l"(d) : "l"(a), "l"(b));
}
__device__ __forceinline__ u64 pk2(float x, float y){
    u64 r; asm("mov.b64 %0, {%1, %2};" : "=l"(r) : "f"(x), "f"(y)); return r;
}
__device__ __forceinline__ float2 upk2(u64 v){
    float2 r; asm("mov.b64 {%0, %1}, %2;" : "=f"(r.x), "=f"(r.y) : "l"(v)); return r;
}

#define EPI_RELU_STORE 0
#define EPI_SCATTER    1
#define EPI_RESID      2
#define EPI_STORE      3

// A-fragment assembly
// AMODE 0: dense rows x 128
// AMODE 1: fused first-message-layer: relu(Pd[dst] + Ps[src] + tail@Wt)   K=128
// AMODE 2: update gather: [h | agg*invdeg | var]                          K=257
template<int AMODE>
__device__ __forceinline__ float4 a_frag(const float* __restrict__ A, int row,
    int k0, int i0, int i1, float4 tl, float invd, float var,
    const float* __restrict__ s_wt)
{
    float4 av = make_float4(0.f,0.f,0.f,0.f);
    if (AMODE == 0){
        av = *(const float4*)&A[row*HH + k0];
    } else if (AMODE == 1){
        float4 pd = *(const float4*)&g_Pd[i0*HH + k0];
        float4 ps = *(const float4*)&g_Ps[i1*HH + k0];
        av.x = pd.x + ps.x; av.y = pd.y + ps.y;
        av.z = pd.z + ps.z; av.w = pd.w + ps.w;
        #pragma unroll
        for (int t = 0; t < 4; t++){
            float tv = (&tl.x)[t];
            const float* wr = &s_wt[t*HH + k0];
            av.x += tv*wr[0]; av.y += tv*wr[1];
            av.z += tv*wr[2]; av.w += tv*wr[3];
        }
        av.x = fmaxf(av.x,0.f); av.y = fmaxf(av.y,0.f);
        av.z = fmaxf(av.z,0.f); av.w = fmaxf(av.w,0.f);
    } else {
        if (k0 < 128){
            av = *(const float4*)&g_h[row*HH + k0];
        } else if (k0 < 256){
            av = *(const float4*)&g_agg[row*HH + (k0-128)];
            av.x *= invd; av.y *= invd; av.z *= invd; av.w *= invd;
        } else if (k0 == 256){
            av = make_float4(var, 0.f, 0.f, 0.f);
        }
    }
    return av;
}

// 128x128 output tile, BK=16, 256 threads, f32x2 FMA, reg-prefetch pipeline
template<int AMODE, int EPI>
__global__ __launch_bounds__(256)
void gemm2(const float* __restrict__ A, const float* __restrict__ W,
           const float* __restrict__ bias, float* __restrict__ out,
           const float* __restrict__ Wt, int rows, int K)
{
    __shared__ float As[16][132];
    __shared__ float Bs[16][128];
    __shared__ float s_wt[4*HH];
    __shared__ int   s_i0[128];
    __shared__ int   s_i1[128];
    __shared__ float4 s_tl[128];
    __shared__ float s_f0[128];
    __shared__ float s_f1[128];

    const int tid  = threadIdx.x;
    const int base = blockIdx.x * 128;

    if (tid < 128){
        int r = base + tid;
        bool v = r < rows;
        int rc = v ? r : rows - 1;
        if (AMODE == 1){
            s_i0[tid] = v ? g_sdst[r] : 0;
            s_i1[tid] = v ? g_ssrc[r] : 0;
            s_tl[tid] = v ? g_tl[r] : make_float4(0.f,0.f,0.f,0.f);
        } else if (AMODE == 2){
            s_f0[tid] = g_invdeg[rc];
            s_f1[tid] = g_var[rc];
        }
    }
    if (AMODE == 1){
        for (int i = tid; i < 4*HH; i += 256) s_wt[i] = Wt[i];
    }
    __syncthreads();

    const int tx = tid & 15;          // output cols tx*8..+7
    const int ty = tid >> 4;          // output rows ty*8..+7
    const int lm = tid >> 2;          // A load row (frag0: lm, frag1: 64+lm)
    const int lc = (tid & 3) * 4;     // A load k offset
    const int bk = tid >> 5;          // B load k row (bk, bk+8)
    const int bj = (tid & 31) * 4;    // B load col

    const int arow0 = min(base + lm,      rows - 1);
    const int arow1 = min(base + 64 + lm, rows - 1);

    int i0a=0,i1a=0,i0b=0,i1b=0; float4 tla={0,0,0,0}, tlb={0,0,0,0};
    float ida=0.f,vaa=0.f,idb=0.f,vab=0.f;
    if (AMODE == 1){
        i0a = s_i0[lm];    i1a = s_i1[lm];    tla = s_tl[lm];
        i0b = s_i0[64+lm]; i1b = s_i1[64+lm]; tlb = s_tl[64+lm];
    } else if (AMODE == 2){
        ida = s_f0[lm];    vaa = s_f1[lm];
        idb = s_f0[64+lm]; vab = s_f1[64+lm];
    }

    u64 acc[4][8];
    #pragma unroll
    for (int i=0;i<4;i++)
        #pragma unroll
        for (int j=0;j<8;j++) acc[i][j]=0ULL;

    const int nkt = (K + 15) >> 4;

    // prefetch tile 0
    float4 ra0, ra1, rb0, rb1;
    {
        int k0 = lc;
        ra0 = a_frag<AMODE>(A, arow0, k0, i0a, i1a, tla, ida, vaa, s_wt);
        ra1 = a_frag<AMODE>(A, arow1, k0, i0b, i1b, tlb, idb, vab, s_wt);
        int kg0 = bk, kg1 = bk + 8;
        rb0 = (kg0 < K) ? *(const float4*)&W[kg0*HH + bj] : make_float4(0,0,0,0);
        rb1 = (kg1 < K) ? *(const float4*)&W[kg1*HH + bj] : make_float4(0,0,0,0);
    }

    for (int kt = 0; kt < nkt; kt++){
        As[lc+0][lm]    = ra0.x; As[lc+1][lm]    = ra0.y;
        As[lc+2][lm]    = ra0.z; As[lc+3][lm]    = ra0.w;
        As[lc+0][64+lm] = ra1.x; As[lc+1][64+lm] = ra1.y;
        As[lc+2][64+lm] = ra1.z; As[lc+3][64+lm] = ra1.w;
        *(float4*)&Bs[bk  ][bj] = rb0;
        *(float4*)&Bs[bk+8][bj] = rb1;
        __syncthreads();

        if (kt + 1 < nkt){
            int k0 = (kt+1)*16 + lc;
            if (AMODE != 0 || true){
                ra0 = (AMODE==0 || k0 < K) ? a_frag<AMODE>(A, arow0, (AMODE==2 && k0>=K)?256:k0, i0a, i1a, tla, ida, vaa, s_wt)
                                           : make_float4(0,0,0,0);
            }
            // simpler re-do with bound handling:
            if (AMODE == 2 && k0 > 256){ ra0 = make_float4(0,0,0,0); }
            else ra0 = a_frag<AMODE>(A, arow0, k0, i0a, i1a, tla, ida, vaa, s_wt);
            if (AMODE == 2 && k0 > 256){ ra1 = make_float4(0,0,0,0); }
            else ra1 = a_frag<AMODE>(A, arow1, k0, i0b, i1b, tlb, idb, vab, s_wt);
            int kg0 = (kt+1)*16 + bk, kg1 = kg0 + 8;
            rb0 = (kg0 < K) ? *(const float4*)&W[kg0*HH + bj] : make_float4(0,0,0,0);
            rb1 = (kg1 < K) ? *(const float4*)&W[kg1*HH + bj] : make_float4(0,0,0,0);
        }

        #pragma unroll
        for (int k=0;k<16;k++){
            union { float4 f; u64 u[2]; } a0, a1, b0, b1;
            a0.f = *(const float4*)&As[k][ty*8];
            a1.f = *(const float4*)&As[k][ty*8+4];
            b0.f = *(const float4*)&Bs[k][tx*8];
            b1.f = *(const float4*)&Bs[k][tx*8+4];
            u64 ap[4] = { a0.u[0], a0.u[1], a1.u[0], a1.u[1] };
            float bsc[8] = { b0.f.x, b0.f.y, b0.f.z, b0.f.w,
                             b1.f.x, b1.f.y, b1.f.z, b1.f.w };
            #pragma unroll
            for (int j=0;j<8;j++){
                u64 bp = pk2(bsc[j], bsc[j]);
                #pragma unroll
                for (int i=0;i<4;i++) fma2(acc[i][j], ap[i], bp);
            }
        }
        __syncthreads();
    }

    // ---- epilogue ----
    float bb[8];
    *(float4*)&bb[0] = *(const float4*)&bias[tx*8];
    *(float4*)&bb[4] = *(const float4*)&bias[tx*8+4];

    if (EPI == EPI_SCATTER){
        float cur[8]; int curd = -1;
        #pragma unroll 1
        for (int i=0;i<8;i++){
            int lrow = ty*8 + i;
            int r = base + lrow;
            if (r >= rows) break;
            float v[8];
            #pragma unroll
            for (int j=0;j<8;j++){
                float2 p = upk2(acc[i>>1][j]);
                float val = ((i&1) ? p.y : p.x) + bb[j];
                v[j] = fmaxf(val, 0.f);
            }
            int d = s_i0[lrow];
            if (d == curd){
                #pragma unroll
                for (int j=0;j<8;j++) cur[j] += v[j];
            } else {
                if (curd >= 0){
                    #pragma unroll
                    for (int j=0;j<8;j++) atomicAdd(&out[curd*HH + tx*8 + j], cur[j]);
                }
                curd = d;
                #pragma unroll
                for (int j=0;j<8;j++) cur[j] = v[j];
            }
        }
        if (curd >= 0){
            #pragma unroll
            for (int j=0;j<8;j++) atomicAdd(&out[curd*HH + tx*8 + j], cur[j]);
        }
    } else {
        #pragma unroll
        for (int i=0;i<8;i++){
            int r = base + ty*8 + i;
            if (r >= rows) continue;
            float v[8];
            #pragma unroll
            for (int j=0;j<8;j++){
                float2 p = upk2(acc[i>>1][j]);
                float val = ((i&1) ? p.y : p.x) + bb[j];
                if (EPI != EPI_STORE) val = fmaxf(val, 0.f);
                v[j] = val;
            }
            if (EPI == EPI_RESID){
                float4 h0 = *(const float4*)&g_h[r*HH + tx*8];
                float4 h1 = *(const float4*)&g_h[r*HH + tx*8+4];
                v[0]+=h0.x; v[1]+=h0.y; v[2]+=h0.z; v[3]+=h0.w;
                v[4]+=h1.x; v[5]+=h1.y; v[6]+=h1.z; v[7]+=h1.w;
            }
            *(float4*)&out[r*HH + tx*8]   = make_float4(v[0],v[1],v[2],v[3]);
            *(float4*)&out[r*HH + tx*8+4] = make_float4(v[4],v[5],v[6],v[7]);
        }
    }
}

// ---------------- small kernels ----------------
__global__ void k_zero(float* __restrict__ p, int n){
    int i = blockIdx.x*blockDim.x + threadIdx.x;
    if (i < n) p[i] = 0.f;
}
__global__ void k_zero_i(int* __restrict__ p, int n){
    int i = blockIdx.x*blockDim.x + threadIdx.x;
    if (i < n) p[i] = 0;
}
__global__ void k_node_pre(const float* __restrict__ pos){
    int n = blockIdx.x*blockDim.x + threadIdx.x;
    if (n < NN) g_var[n] = pos[n*3+0];
}
__global__ void k_hist(const int* __restrict__ dst){
    int e = blockIdx.x*blockDim.x + threadIdx.x;
    if (e < NE) atomicAdd(&g_cnt[dst[e]], 1);
}
__global__ __launch_bounds__(1024)
void k_scan(){
    __shared__ float sdata[1024];   // float is exact for counts <= 600000? use int
    __shared__ int sd[1024];
    int t = threadIdx.x;
    const int chunk = (NN + 1023) / 1024;
    int beg = t * chunk, end = min(beg + chunk, NN);
    int s = 0;
    for (int i = beg; i < end; i++) s += g_cnt[i];
    sd[t] = s;
    __syncthreads();
    int v = s;
    for (int off = 1; off < 1024; off <<= 1){
        int add = (t >= off) ? sd[t-off] : 0;
        __syncthreads();
        sd[t] += add;
        __syncthreads();
    }
    int run = sd[t] - v;   // exclusive prefix of this thread's chunk
    for (int i = beg; i < end; i++){
        int c = g_cnt[i];
        g_woff[i] = run;
        g_invdeg[i] = 1.f / fmaxf((float)c, 1.f);
        run += c;
    }
    (void)sdata;
}
__global__ void k_scatter(const float* __restrict__ u, const float* __restrict__ pos,
                          const int* __restrict__ src, const int* __restrict__ dst){
    int e = blockIdx.x*blockDim.x + threadIdx.x;
    if (e < NE){
        int s = src[e], d = dst[e];
        int p = atomicAdd(&g_woff[d], 1);
        g_sdst[p] = d;
        g_ssrc[p] = s;
        g_tl[p] = make_float4(u[d]-u[s],
                              pos[d*3+1]-pos[s*3+1],
                              pos[d*3+2]-pos[s*3+2],
                              pos[d*3+0]);
    }
}
__global__ void k_h0(const float* __restrict__ u, const float* __restrict__ pos,
                     const float* __restrict__ W1, const float* __restrict__ b1){
    int idx = blockIdx.x*blockDim.x + threadIdx.x;
    if (idx < NN*HH){
        int n = idx >> 7, j = idx & 127;
        g_hn[idx] = u[n]       * W1[j]
                  + pos[n*3+1] * W1[128+j]
                  + pos[n*3+2] * W1[256+j]
                  + pos[n*3+0] * W1[384+j]
                  + b1[j];
    }
}
__global__ void k_bn_zero(){
    int t = threadIdx.x;
    if (t < HH){ g_sum[t]=0.f; g_sumsq[t]=0.f; }
}
__global__ void k_bn_stats(const float* __restrict__ x){
    int j = threadIdx.x;
    int r0 = blockIdx.x * 256;
    int rend = min(r0 + 256, NN);
    float s = 0.f, s2 = 0.f;
    for (int r = r0; r < rend; r++){
        float v = x[r*HH + j];
        s += v; s2 += v*v;
    }
    atomicAdd(&g_sum[j], s);
    atomicAdd(&g_sumsq[j], s2);
}
__global__ void k_bn_fin(const float* __restrict__ g, const float* __restrict__ be){
    int j = threadIdx.x;
    float mu  = g_sum[j]   * (1.f/NN);
    float var = g_sumsq[j] * (1.f/NN) - mu*mu;
    float a = g[j] * rsqrtf(var + 1e-5f);
    g_ba[j] = a;
    g_bc[j] = be[j] - a*mu;
}
template<bool RELU>
__global__ void k_bn_apply(const float* __restrict__ x, float* __restrict__ y){
    int i4 = blockIdx.x*blockDim.x + threadIdx.x;
    if (i4 < NN*HH/4){
        int j = (i4*4) & 127;
        float4 v = *(const float4*)&x[i4*4];
        float4 a = *(const float4*)&g_ba[j];
        float4 c = *(const float4*)&g_bc[j];
        float4 o = make_float4(a.x*v.x+c.x, a.y*v.y+c.y, a.z*v.z+c.z, a.w*v.w+c.w);
        if (RELU){
            o.x=fmaxf(o.x,0.f); o.y=fmaxf(o.y,0.f);
            o.z=fmaxf(o.z,0.f); o.w=fmaxf(o.w,0.f);
        }
        *(float4*)&y[i4*4] = o;
    }
}

// ---------------- CNN head ----------------
__global__ __launch_bounds__(64)
void k_cnn(const float* __restrict__ c1W, const float* __restrict__ c1b,
           const float* __restrict__ c2W, const float* __restrict__ c2b,
           const float* __restrict__ c3W, const float* __restrict__ c3b,
           float* __restrict__ out){
    __shared__ float sx[64][129];
    __shared__ float w1[64], w2[384], w3[64], b1[4], b2[8], b3[1];
    int tid = threadIdx.x;
    int base = blockIdx.x * 64;

    w1[tid] = c1W[tid];
    w3[tid] = c3W[tid];
    for (int i = tid; i < 384; i += 64) w2[i] = c2W[i];
    if (tid < 4) b1[tid] = c1b[tid];
    if (tid < 8) b2[tid] = c2b[tid];
    if (tid == 0) b3[0] = c3b[0];

    for (int r = 0; r < 64; r++){
        int row = base + r; int rr = row < NN ? row : NN-1;
        sx[r][tid]    = g_h[rr*HH + tid];
        sx[r][tid+64] = g_h[rr*HH + tid + 64];
    }
    __syncthreads();

    int node = base + tid;
    if (node >= NN) return;

    float o1[4][38];
    #pragma unroll
    for (int c = 0; c < 4; c++)
        for (int p = 0; p < 38; p++){
            float s = b1[c];
            #pragma unroll
            for (int k = 0; k < 16; k++) s += sx[tid][3*p+k] * w1[c*16+k];
            o1[c][p] = fmaxf(s, 0.f);
        }
    float o2[8][9];
    for (int o = 0; o < 8; o++)
        for (int q = 0; q < 9; q++){
            float s = b2[o];
            for (int c = 0; c < 4; c++)
                #pragma unroll
                for (int k = 0; k < 12; k++) s += o1[c][3*q+k] * w2[(o*4+c)*12+k];
            o2[o][q] = fmaxf(s, 0.f);
        }
    float s = b3[0];
    #pragma unroll
    for (int o = 0; o < 8; o++)
        #pragma unroll
        for (int k = 0; k < 8; k++) s += o2[o][k] * w3[o*8+k];

    out[node] = 0.001f * s;
}

// ---------------- launch ----------------
extern "C" void kernel_launch(void* const* d_in, const int* in_sizes, int n_in,
                              void* d_out, int out_size)
{
    const float* u      = (const float*)d_in[0];
    const float* pos    = (const float*)d_in[1];
    const int*   ei     = (const int*)  d_in[2];
    const int*   src    = ei;
    const int*   dst    = ei + NE;
    const float* emb_W1 = (const float*)d_in[3];
    const float* emb_b1 = (const float*)d_in[4];
    const float* emb_g1 = (const float*)d_in[5];
    const float* emb_be1= (const float*)d_in[6];
    const float* emb_W2 = (const float*)d_in[7];
    const float* emb_b2 = (const float*)d_in[8];
    const float* emb_g2 = (const float*)d_in[9];
    const float* emb_be2= (const float*)d_in[10];
    const float* m1W    = (const float*)d_in[11];
    const float* m1b    = (const float*)d_in[12];
    const float* m2W    = (const float*)d_in[13];
    const float* m2b    = (const float*)d_in[14];
    const float* u1W    = (const float*)d_in[15];
    const float* u1b    = (const float*)d_in[16];
    const float* u2W    = (const float*)d_in[17];
    const float* u2b    = (const float*)d_in[18];
    const float* bng    = (const float*)d_in[19];
    const float* bnb    = (const float*)d_in[20];
    const float* c1W    = (const float*)d_in[21];
    const float* c1b    = (const float*)d_in[22];
    const float* c2W    = (const float*)d_in[23];
    const float* c2b    = (const float*)d_in[24];
    const float* c3W    = (const float*)d_in[25];
    const float* c3b    = (const float*)d_in[26];
    float* out = (float*)d_out;

    float *p_h, *p_hn, *p_up, *p_agg, *p_Pd, *p_Ps, *p_zero;
    int *p_cnt;
    cudaGetSymbolAddress((void**)&p_h,    g_h);
    cudaGetSymbolAddress((void**)&p_hn,   g_hn);
    cudaGetSymbolAddress((void**)&p_up,   g_up);
    cudaGetSymbolAddress((void**)&p_agg,  g_agg);
    cudaGetSymbolAddress((void**)&p_Pd,   g_Pd);
    cudaGetSymbolAddress((void**)&p_Ps,   g_Ps);
    cudaGetSymbolAddress((void**)&p_zero, g_zero);
    cudaGetSymbolAddress((void**)&p_cnt,  g_cnt);

    const int GN  = (NN + 127) / 128;
    const int GE  = (NE + 127) / 128;
    const int ELT = (NN*HH + 255) / 256;

    auto bn = [&](const float* x, float* y, const float* g, const float* be, bool relu){
        k_bn_zero<<<1,128>>>();
        k_bn_stats<<<(NN+255)/256,128>>>(x);
        k_bn_fin<<<1,128>>>(g, be);
        if (relu) k_bn_apply<true ><<<(NN*HH/4+255)/256,256>>>(x, y);
        else      k_bn_apply<false><<<(NN*HH/4+255)/256,256>>>(x, y);
    };

    // ---- preprocessing: node var, degree histogram, counting sort by dst ----
    k_node_pre<<<(NN+255)/256,256>>>(pos);
    k_zero_i<<<(NN+255)/256,256>>>(p_cnt, NN);
    k_hist<<<(NE+255)/256,256>>>(dst);
    k_scan<<<1,1024>>>();
    k_scatter<<<(NE+255)/256,256>>>(u, pos, src, dst);

    // ---- embedding ----
    k_h0<<<(NN*HH+255)/256,256>>>(u, pos, emb_W1, emb_b1);
    bn(p_hn, p_h, emb_g1, emb_be1, true);
    gemm2<0,EPI_STORE><<<GN,256>>>(p_h, emb_W2, emb_b2, p_hn, nullptr, NN, 128);
    bn(p_hn, p_h, emb_g2, emb_be2, false);

    // ---- message-passing layers ----
    for (int i = 0; i < LL; i++){
        const float* Wd = m1W + (size_t)i*260*128;            // rows 0..127
        const float* Ws = Wd + 128*128;                        // rows 128..255
        const float* Wt = Wd + 256*128;                        // rows 256..259
        // node-side precompute of first message layer
        gemm2<0,EPI_STORE><<<GN,256>>>(p_h, Wd, m1b + i*128, p_Pd, nullptr, NN, 128);
        gemm2<0,EPI_STORE><<<GN,256>>>(p_h, Ws, p_zero,      p_Ps, nullptr, NN, 128);
        // fused edge kernel: assemble relu(Pd[dst]+Ps[src]+tail@Wt), GEMM by m2_W,
        // relu, merged atomic scatter into agg (dst-sorted rows)
        k_zero<<<ELT,256>>>(p_agg, NN*HH);
        gemm2<1,EPI_SCATTER><<<GE,256>>>(nullptr, m2W + (size_t)i*128*128,
                                         m2b + i*128, p_agg, Wt, NE, 128);
        // update MLP
        gemm2<2,EPI_RELU_STORE><<<GN,256>>>(nullptr, u1W + (size_t)i*257*128,
                                            u1b + i*128, p_up, nullptr, NN, 257);
        gemm2<0,EPI_RESID><<<GN,256>>>(p_up, u2W + (size_t)i*128*128,
                                       u2b + i*128, p_hn, nullptr, NN, 128);
        bn(p_hn, p_h, bng + i*128, bnb + i*128, false);
    }

    // ---- CNN head ----
    k_cnn<<<(NN+63)/64,64>>>(c1W, c1b, c2W, c2b, c3W, c3b, out);
}

// round 5
// speedup vs baseline: 4.3524x; 1.9731x over previous
#include <cuda_runtime.h>
#include <cuda_bf16.h>
#include <cstdint>

#define NN 50000
#define NE 600000
#define HH 128
#define LL 6

typedef unsigned long long u64;
typedef unsigned int u32;

// ---------------- scratch (static device buffers; no allocation) ----------------
__device__ float g_h  [NN*HH];
__device__ float g_hn [NN*HH];
__device__ float g_up [NN*HH];
__device__ float g_agg[NN*HH];
__device__ float g_Pd [NN*HH];
__device__ float g_Ps [NN*HH];
__device__ float4 g_tl[NE];
__device__ int   g_sdst[NE];
__device__ int   g_ssrc[NE];
__device__ int   g_cnt[NN];
__device__ int   g_woff[NN];
__device__ int   g_bsum[128];
__device__ float g_invdeg[NN];
__device__ float g_var[NN];
__device__ float g_sum[HH];
__device__ float g_sumsq[HH];
__device__ float g_ba[HH];
__device__ float g_bc[HH];
__device__ float g_zero[HH];            // stays zero
// B weight images: 43 chunks x 64KB (hi 32KB [n][k] bf16, then lo 32KB)
#define NCHUNK_TOT 43
__device__ char g_Bimg[(size_t)NCHUNK_TOT * 65536];

// ---------------- PTX helpers (baseline ISA only: ldmatrix + mma.sync) ----------------
__device__ __forceinline__ u32 smem_u32(const void* p){
    u32 a; asm("{ .reg .u64 t; cvta.to.shared.u64 t, %1; cvt.u32.u64 %0, t; }" : "=r"(a) : "l"(p));
    return a;
}
__device__ __forceinline__ void ldsm4(u32 &r0, u32 &r1, u32 &r2, u32 &r3, u32 addr){
    asm volatile("ldmatrix.sync.aligned.m8n8.x4.shared.b16 {%0,%1,%2,%3}, [%4];"
        : "=r"(r0), "=r"(r1), "=r"(r2), "=r"(r3) : "r"(addr));
}
__device__ __forceinline__ void mma16816(float4 &d, const u32* a, u32 b0, u32 b1){
    asm volatile("mma.sync.aligned.m16n8k16.row.col.f32.bf16.bf16.f32 "
        "{%0,%1,%2,%3}, {%4,%5,%6,%7}, {%8,%9}, {%0,%1,%2,%3};"
        : "+f"(d.x), "+f"(d.y), "+f"(d.z), "+f"(d.w)
        : "r"(a[0]), "r"(a[1]), "r"(a[2]), "r"(a[3]), "r"(b0), "r"(b1));
}

#define EPI_RELU_STORE 0
#define EPI_SCATTER    1
#define EPI_RESID      2
#define EPI_STORE      3

// dynamic smem layout (bytes)
// A tiles: 128 rows x 40 halves (80B stride, conflict-free for ldmatrix)
// B tiles: 128 n-rows x 136 halves (272B stride, conflict-free)
#define A_HI 0
#define A_LO 10240
#define B_HI 20480
#define B_LO 55296
#define WT_OFF 90112
#define I0_OFF 92160
#define I1_OFF 92672
#define TL_OFF 93184
#define F0_OFF 95232
#define F1_OFF 95744
#define SMEM_BYTES 96256
// s_red (128x132 floats = 67584 B) overlays A+B after compute

// A-fragment assembly (8 consecutive k-values for one row)
// AMODE 0: dense A rows x 128
// AMODE 1: edge fused: relu(Pd[dst] + Ps[src] + tail@Wt)     (K=128)
// AMODE 2: update: [h | agg*invdeg | var | 0-pad]            (K=257)
template<int AMODE>
__device__ __forceinline__ void a_frag8(const float* __restrict__ A, int arow,
    int kglob, int i0, int i1, float4 tl, float invd, float var,
    const float* __restrict__ s_wt, float* v)
{
    if (AMODE == 0){
        float4 a0 = *(const float4*)&A[(size_t)arow*128 + kglob];
        float4 a1 = *(const float4*)&A[(size_t)arow*128 + kglob + 4];
        v[0]=a0.x; v[1]=a0.y; v[2]=a0.z; v[3]=a0.w;
        v[4]=a1.x; v[5]=a1.y; v[6]=a1.z; v[7]=a1.w;
    } else if (AMODE == 1){
        float4 p0 = *(const float4*)&g_Pd[(size_t)i0*HH + kglob];
        float4 p1 = *(const float4*)&g_Pd[(size_t)i0*HH + kglob + 4];
        float4 q0 = *(const float4*)&g_Ps[(size_t)i1*HH + kglob];
        float4 q1 = *(const float4*)&g_Ps[(size_t)i1*HH + kglob + 4];
        v[0]=p0.x+q0.x; v[1]=p0.y+q0.y; v[2]=p0.z+q0.z; v[3]=p0.w+q0.w;
        v[4]=p1.x+q1.x; v[5]=p1.y+q1.y; v[6]=p1.z+q1.z; v[7]=p1.w+q1.w;
        #pragma unroll
        for (int t = 0; t < 4; t++){
            float tv = (&tl.x)[t];
            const float* wr = &s_wt[t*HH + kglob];
            #pragma unroll
            for (int kk = 0; kk < 8; kk++) v[kk] += tv * wr[kk];
        }
        #pragma unroll
        for (int kk = 0; kk < 8; kk++) v[kk] = fmaxf(v[kk], 0.f);
    } else {
        if (kglob < 128){
            float4 a0 = *(const float4*)&g_h[(size_t)arow*HH + kglob];
            float4 a1 = *(const float4*)&g_h[(size_t)arow*HH + kglob + 4];
            v[0]=a0.x; v[1]=a0.y; v[2]=a0.z; v[3]=a0.w;
            v[4]=a1.x; v[5]=a1.y; v[6]=a1.z; v[7]=a1.w;
        } else if (kglob < 256){
            float4 a0 = *(const float4*)&g_agg[(size_t)arow*HH + (kglob-128)];
            float4 a1 = *(const float4*)&g_agg[(size_t)arow*HH + (kglob-128) + 4];
            v[0]=a0.x*invd; v[1]=a0.y*invd; v[2]=a0.z*invd; v[3]=a0.w*invd;
            v[4]=a1.x*invd; v[5]=a1.y*invd; v[6]=a1.z*invd; v[7]=a1.w*invd;
        } else {
            #pragma unroll
            for (int kk = 0; kk < 8; kk++) v[kk] = 0.f;
            if (kglob == 256) v[0] = var;
        }
    }
}

// ---------------- tensor-core GEMM via mma.sync: 128x128 tile per CTA ----------------
template<int AMODE, int EPI>
__global__ __launch_bounds__(256)
void gemm_mma(const float* __restrict__ A, const char* __restrict__ Bimg,
              const float* __restrict__ bias, float* __restrict__ out,
              const float* __restrict__ Wt, int rows, int K, int nchunks)
{
    extern __shared__ __align__(16) char smem[];
    const u32 sb  = smem_u32(smem);
    const int tid = threadIdx.x;
    const int wid = tid >> 5;
    const int lane = tid & 31;
    const int base = blockIdx.x * 128;

    int*    s_i0 = (int*)   (smem + I0_OFF);
    int*    s_i1 = (int*)   (smem + I1_OFF);
    float4* s_tl = (float4*)(smem + TL_OFF);
    float*  s_f0 = (float*) (smem + F0_OFF);
    float*  s_f1 = (float*) (smem + F1_OFF);
    float*  s_wt = (float*) (smem + WT_OFF);

    if (tid < 128){
        int r = base + tid;
        if (AMODE == 1){
            bool v = r < rows;
            s_i0[tid] = v ? g_sdst[r] : 0;
            s_i1[tid] = v ? g_ssrc[r] : 0;
            s_tl[tid] = v ? g_tl[r]   : make_float4(0.f,0.f,0.f,0.f);
        } else if (AMODE == 2){
            int rc = min(r, rows - 1);
            s_f0[tid] = g_invdeg[rc];
            s_f1[tid] = g_var[rc];
        }
    }
    if (AMODE == 1){
        for (int i = tid; i < 4*HH; i += 256) s_wt[i] = Wt[i];
    }
    __syncthreads();

    const int warp_m = wid & 3;          // 4 warps over M
    const int warp_n = wid >> 2;         // 2 warps over N
    const int qi = lane & 7, qd = lane >> 3;

    // ldmatrix per-thread base addresses
    const u32 aab = sb + A_HI + (u32)((warp_m*32 + (qd&1)*8 + qi)*80 + (qd>>1)*16);
    const u32 bab = sb + B_HI + (u32)((warp_n*64 + (qd>>1)*8 + qi)*272 + (qd&1)*16);

    float4 acc[2][8];
    #pragma unroll
    for (int i=0;i<2;i++)
        #pragma unroll
        for (int j=0;j<8;j++) acc[i][j] = make_float4(0.f,0.f,0.f,0.f);

    for (int sc = 0; sc < nchunks; sc++){
        __syncthreads();                  // previous compute done before B overwrite
        // ---- load B superchunk into padded smem (hi+lo) ----
        const uint4* bsrc = (const uint4*)(Bimg + (size_t)sc * 65536);
        #pragma unroll 4
        for (int i = tid; i < 2048; i += 256){
            int row = i >> 4, c = i & 15;
            *(uint4*)(smem + B_HI + row*272 + c*16) = bsrc[i];
            *(uint4*)(smem + B_LO + row*272 + c*16) = bsrc[2048 + i];
        }
        const int nsub = min(4, (K - sc*128 + 31) >> 5);
        for (int sub = 0; sub < nsub; sub++){
            __syncthreads();              // A free (prev compute) / B visible (sub 0)
            // ---- assemble A 128x32 into split-bf16 smem ----
            #pragma unroll 1
            for (int g = tid; g < 512; g += 256){
                int row = g >> 2;
                int k0l = (g & 3) * 8;
                int kglob = sc*128 + sub*32 + k0l;
                int arow = min(base + row, rows - 1);
                float v[8];
                a_frag8<AMODE>(A, arow, kglob,
                               AMODE==1 ? s_i0[row] : 0,
                               AMODE==1 ? s_i1[row] : 0,
                               AMODE==1 ? s_tl[row] : make_float4(0,0,0,0),
                               AMODE==2 ? s_f0[row] : 0.f,
                               AMODE==2 ? s_f1[row] : 0.f,
                               s_wt, v);
                u32 hw[4], lw[4];
                #pragma unroll
                for (int q = 0; q < 4; q++){
                    __nv_bfloat16 h0 = __float2bfloat16(v[2*q]);
                    __nv_bfloat16 h1 = __float2bfloat16(v[2*q+1]);
                    __nv_bfloat16 l0 = __float2bfloat16(v[2*q]   - __bfloat162float(h0));
                    __nv_bfloat16 l1 = __float2bfloat16(v[2*q+1] - __bfloat162float(h1));
                    hw[q] = (u32)__bfloat16_as_ushort(h0) | ((u32)__bfloat16_as_ushort(h1) << 16);
                    lw[q] = (u32)__bfloat16_as_ushort(l0) | ((u32)__bfloat16_as_ushort(l1) << 16);
                }
                u32 aoff = (u32)(row*80 + k0l*2);
                *(uint4*)(smem + A_HI + aoff) = make_uint4(hw[0],hw[1],hw[2],hw[3]);
                *(uint4*)(smem + A_LO + aoff) = make_uint4(lw[0],lw[1],lw[2],lw[3]);
            }
            __syncthreads();
            // ---- compute 2 k-atoms (k16 each) ----
            #pragma unroll
            for (int ka = 0; ka < 2; ka++){
                u32 ah[2][4], al[2][4];
                u32 ab = aab + ka*32;
                ldsm4(ah[0][0],ah[0][1],ah[0][2],ah[0][3], ab);
                ldsm4(ah[1][0],ah[1][1],ah[1][2],ah[1][3], ab + 1280);
                ldsm4(al[0][0],al[0][1],al[0][2],al[0][3], ab + 10240);
                ldsm4(al[1][0],al[1][1],al[1][2],al[1][3], ab + 11520);
                u32 bb0 = bab + (u32)((sub*32 + ka*16) * 2);
                #pragma unroll
                for (int p = 0; p < 4; p++){
                    u32 h0,h1,h2,h3, l0,l1,l2,l3;
                    ldsm4(h0,h1,h2,h3, bb0 + p*4352);
                    ldsm4(l0,l1,l2,l3, bb0 + p*4352 + 34816);
                    #pragma unroll
                    for (int am = 0; am < 2; am++){
                        mma16816(acc[am][2*p],   ah[am], h0, h1);
                        mma16816(acc[am][2*p],   al[am], h0, h1);
                        mma16816(acc[am][2*p],   ah[am], l0, l1);
                        mma16816(acc[am][2*p+1], ah[am], h2, h3);
                        mma16816(acc[am][2*p+1], al[am], h2, h3);
                        mma16816(acc[am][2*p+1], ah[am], l2, l3);
                    }
                }
            }
        }
    }

    // ---- dump accumulators to smem staging tile (overlays A/B) ----
    __syncthreads();
    float* s_red = (float*)smem;
    #pragma unroll
    for (int am = 0; am < 2; am++)
        #pragma unroll
        for (int na = 0; na < 8; na++){
            int m0 = warp_m*32 + am*16 + (lane >> 2);
            int n0 = warp_n*64 + na*8 + (lane & 3)*2;
            float4 c = acc[am][na];
            *(float2*)&s_red[m0*132 + n0]     = make_float2(c.x, c.y);
            *(float2*)&s_red[(m0+8)*132 + n0] = make_float2(c.z, c.w);
        }
    __syncthreads();

    // ---------------- epilogue ----------------
    if (EPI == EPI_SCATTER){
        // bias + relu in place
        for (int i = tid; i < 4096; i += 256){
            int row = i >> 5, c4 = (i & 31)*4;
            float4 v  = *(float4*)&s_red[row*132 + c4];
            float4 bb = *(const float4*)&bias[c4];
            v.x = fmaxf(v.x + bb.x, 0.f); v.y = fmaxf(v.y + bb.y, 0.f);
            v.z = fmaxf(v.z + bb.z, 0.f); v.w = fmaxf(v.w + bb.w, 0.f);
            *(float4*)&s_red[row*132 + c4] = v;
        }
        __shared__ int s_nh;
        __shared__ int s_hd[128];
        if (tid == 0) s_nh = 0;
        __syncthreads();
        if (tid < 128){
            int r = base + tid;
            if (r < rows){
                bool head = (tid == 0) || (s_i0[tid] != s_i0[tid-1]);
                if (head){ int p = atomicAdd(&s_nh, 1); s_hd[p] = tid; }
            }
        }
        __syncthreads();
        int nh = s_nh;
        for (int item = tid; item < nh*32; item += 256){
            int h = s_hd[item >> 5];
            int strip = (item & 31) * 4;
            int d = s_i0[h];
            float a0=0.f, a1=0.f, a2=0.f, a3=0.f;
            int rr = h;
            while (rr < 128 && (base + rr) < rows && s_i0[rr] == d){
                float* rp = &s_red[rr*132 + strip];
                a0 += rp[0]; a1 += rp[1]; a2 += rp[2]; a3 += rp[3];
                rr++;
            }
            atomicAdd(&out[(size_t)d*HH + strip + 0], a0);
            atomicAdd(&out[(size_t)d*HH + strip + 1], a1);
            atomicAdd(&out[(size_t)d*HH + strip + 2], a2);
            atomicAdd(&out[(size_t)d*HH + strip + 3], a3);
        }
    } else {
        for (int i = tid; i < 4096; i += 256){
            int row = i >> 5, c4 = (i & 31)*4;
            int r = base + row;
            if (r >= rows) continue;
            float4 v  = *(float4*)&s_red[row*132 + c4];
            float4 bb = *(const float4*)&bias[c4];
            v.x += bb.x; v.y += bb.y; v.z += bb.z; v.w += bb.w;
            if (EPI != EPI_STORE){
                v.x = fmaxf(v.x, 0.f); v.y = fmaxf(v.y, 0.f);
                v.z = fmaxf(v.z, 0.f); v.w = fmaxf(v.w, 0.f);
            }
            if (EPI == EPI_RESID){
                float4 hv = *(const float4*)&g_h[(size_t)r*HH + c4];
                v.x += hv.x; v.y += hv.y; v.z += hv.z; v.w += hv.w;
            }
            *(float4*)&out[(size_t)r*HH + c4] = v;
        }
    }
}

// ---------------- weight image prep: [n][k] split-bf16 linear ----------------
__global__ void k_prepB(const float* __restrict__ W, int Krows, int nchunks,
                        char* __restrict__ img){
    int idx = blockIdx.x*blockDim.x + threadIdx.x;
    int total = nchunks * 16384;
    if (idx >= total) return;
    int c = idx >> 14;
    int rem = idx & 16383;
    int n = rem & 127;
    int kcol = rem >> 7;
    int k = c*128 + kcol;
    float w = (k < Krows) ? W[(size_t)k*128 + n] : 0.f;
    __nv_bfloat16 bh = __float2bfloat16(w);
    __nv_bfloat16 bl = __float2bfloat16(w - __bfloat162float(bh));
    char* cb = img + (size_t)c*65536;
    ((__nv_bfloat16*)cb)[n*128 + kcol]           = bh;
    ((__nv_bfloat16*)(cb + 32768))[n*128 + kcol] = bl;
}

// ---------------- small kernels ----------------
__global__ void k_zero(float* __restrict__ p, int n){
    int i = blockIdx.x*blockDim.x + threadIdx.x;
    if (i < n) p[i] = 0.f;
}
__global__ void k_zero_i(int* __restrict__ p, int n){
    int i = blockIdx.x*blockDim.x + threadIdx.x;
    if (i < n) p[i] = 0;
}
__global__ void k_node_pre(const float* __restrict__ pos){
    int n = blockIdx.x*blockDim.x + threadIdx.x;
    if (n < NN) g_var[n] = pos[n*3+0];
}
__global__ void k_hist(const int* __restrict__ dst){
    int e = blockIdx.x*blockDim.x + threadIdx.x;
    if (e < NE) atomicAdd(&g_cnt[dst[e]], 1);
}
#define SBK 512
__global__ __launch_bounds__(SBK)
void k_scanA(){
    __shared__ int sd[SBK];
    int b = blockIdx.x, t = threadIdx.x;
    int i = b*SBK + t;
    int c = (i < NN) ? g_cnt[i] : 0;
    sd[t] = c; __syncthreads();
    for (int off = 1; off < SBK; off <<= 1){
        int add = (t >= off) ? sd[t-off] : 0;
        __syncthreads();
        sd[t] += add;
        __syncthreads();
    }
    if (i < NN) g_woff[i] = sd[t] - c;
    if (t == SBK-1) g_bsum[b] = sd[t];
}
__global__ void k_scanB(int nb){
    __shared__ int s[128];
    int t = threadIdx.x;
    s[t] = (t < nb) ? g_bsum[t] : 0;
    __syncthreads();
    if (t == 0){
        int run = 0;
        for (int i = 0; i < nb; i++){ int c = s[i]; s[i] = run; run += c; }
    }
    __syncthreads();
    if (t < nb) g_bsum[t] = s[t];
}
__global__ void k_scanC(){
    int i = blockIdx.x*blockDim.x + threadIdx.x;
    if (i < NN){
        g_woff[i] += g_bsum[i / SBK];
        g_invdeg[i] = 1.f / fmaxf((float)g_cnt[i], 1.f);
    }
}
__global__ void k_scatter(const float* __restrict__ u, const float* __restrict__ pos,
                          const int* __restrict__ src, const int* __restrict__ dst){
    int e = blockIdx.x*blockDim.x + threadIdx.x;
    if (e < NE){
        int s = src[e], d = dst[e];
        int p = atomicAdd(&g_woff[d], 1);
        g_sdst[p] = d;
        g_ssrc[p] = s;
        g_tl[p] = make_float4(u[d]-u[s],
                              pos[d*3+1]-pos[s*3+1],
                              pos[d*3+2]-pos[s*3+2],
                              pos[d*3+0]);
    }
}
__global__ void k_h0(const float* __restrict__ u, const float* __restrict__ pos,
                     const float* __restrict__ W1, const float* __restrict__ b1){
    int idx = blockIdx.x*blockDim.x + threadIdx.x;
    if (idx < NN*HH){
        int n = idx >> 7, j = idx & 127;
        g_hn[idx] = u[n]       * W1[j]
                  + pos[n*3+1] * W1[128+j]
                  + pos[n*3+2] * W1[256+j]
                  + pos[n*3+0] * W1[384+j]
                  + b1[j];
    }
}
__global__ void k_bn_zero(){
    int t = threadIdx.x;
    if (t < HH){ g_sum[t]=0.f; g_sumsq[t]=0.f; }
}
__global__ void k_bn_stats(const float* __restrict__ x){
    int j = threadIdx.x;
    int r0 = blockIdx.x * 256;
    int rend = min(r0 + 256, NN);
    float s = 0.f, s2 = 0.f;
    for (int r = r0; r < rend; r++){
        float v = x[(size_t)r*HH + j];
        s += v; s2 += v*v;
    }
    atomicAdd(&g_sum[j], s);
    atomicAdd(&g_sumsq[j], s2);
}
__global__ void k_bn_fin(const float* __restrict__ g, const float* __restrict__ be){
    int j = threadIdx.x;
    float mu  = g_sum[j]   * (1.f/NN);
    float var = g_sumsq[j] * (1.f/NN) - mu*mu;
    float a = g[j] * rsqrtf(var + 1e-5f);
    g_ba[j] = a;
    g_bc[j] = be[j] - a*mu;
}
template<bool RELU>
__global__ void k_bn_apply(const float* __restrict__ x, float* __restrict__ y){
    int i4 = blockIdx.x*blockDim.x + threadIdx.x;
    if (i4 < NN*HH/4){
        int j = (i4*4) & 127;
        float4 v = *(const float4*)&x[i4*4];
        float4 a = *(const float4*)&g_ba[j];
        float4 c = *(const float4*)&g_bc[j];
        float4 o = make_float4(a.x*v.x+c.x, a.y*v.y+c.y, a.z*v.z+c.z, a.w*v.w+c.w);
        if (RELU){
            o.x=fmaxf(o.x,0.f); o.y=fmaxf(o.y,0.f);
            o.z=fmaxf(o.z,0.f); o.w=fmaxf(o.w,0.f);
        }
        *(float4*)&y[i4*4] = o;
    }
}

// ---------------- CNN head ----------------
__global__ __launch_bounds__(64)
void k_cnn(const float* __restrict__ c1W, const float* __restrict__ c1b,
           const float* __restrict__ c2W, const float* __restrict__ c2b,
           const float* __restrict__ c3W, const float* __restrict__ c3b,
           float* __restrict__ out){
    __shared__ float sx[64][129];
    __shared__ float w1[64], w2[384], w3[64], b1[4], b2[8], b3[1];
    int tid = threadIdx.x;
    int base = blockIdx.x * 64;

    w1[tid] = c1W[tid];
    w3[tid] = c3W[tid];
    for (int i = tid; i < 384; i += 64) w2[i] = c2W[i];
    if (tid < 4) b1[tid] = c1b[tid];
    if (tid < 8) b2[tid] = c2b[tid];
    if (tid == 0) b3[0] = c3b[0];

    for (int r = 0; r < 64; r++){
        int row = base + r; int rr = row < NN ? row : NN-1;
        sx[r][tid]    = g_h[(size_t)rr*HH + tid];
        sx[r][tid+64] = g_h[(size_t)rr*HH + tid + 64];
    }
    __syncthreads();

    int node = base + tid;
    if (node >= NN) return;

    float o1[4][38];
    #pragma unroll
    for (int c = 0; c < 4; c++)
        for (int p = 0; p < 38; p++){
            float s = b1[c];
            #pragma unroll
            for (int k = 0; k < 16; k++) s += sx[tid][3*p+k] * w1[c*16+k];
            o1[c][p] = fmaxf(s, 0.f);
        }
    float o2[8][9];
    for (int o = 0; o < 8; o++)
        for (int q = 0; q < 9; q++){
            float s = b2[o];
            for (int c = 0; c < 4; c++)
                #pragma unroll
                for (int k = 0; k < 12; k++) s += o1[c][3*q+k] * w2[(o*4+c)*12+k];
            o2[o][q] = fmaxf(s, 0.f);
        }
    float s = b3[0];
    #pragma unroll
    for (int o = 0; o < 8; o++)
        #pragma unroll
        for (int k = 0; k < 8; k++) s += o2[o][k] * w3[o*8+k];

    out[node] = 0.001f * s;
}

// ---------------- launch ----------------
extern "C" void kernel_launch(void* const* d_in, const int* in_sizes, int n_in,
                              void* d_out, int out_size)
{
    const float* u      = (const float*)d_in[0];
    const float* pos    = (const float*)d_in[1];
    const int*   ei     = (const int*)  d_in[2];
    const int*   src    = ei;
    const int*   dst    = ei + NE;
    const float* emb_W1 = (const float*)d_in[3];
    const float* emb_b1 = (const float*)d_in[4];
    const float* emb_g1 = (const float*)d_in[5];
    const float* emb_be1= (const float*)d_in[6];
    const float* emb_W2 = (const float*)d_in[7];
    const float* emb_b2 = (const float*)d_in[8];
    const float* emb_g2 = (const float*)d_in[9];
    const float* emb_be2= (const float*)d_in[10];
    const float* m1W    = (const float*)d_in[11];
    const float* m1b    = (const float*)d_in[12];
    const float* m2W    = (const float*)d_in[13];
    const float* m2b    = (const float*)d_in[14];
    const float* u1W    = (const float*)d_in[15];
    const float* u1b    = (const float*)d_in[16];
    const float* u2W    = (const float*)d_in[17];
    const float* u2b    = (const float*)d_in[18];
    const float* bng    = (const float*)d_in[19];
    const float* bnb    = (const float*)d_in[20];
    const float* c1W    = (const float*)d_in[21];
    const float* c1b    = (const float*)d_in[22];
    const float* c2W    = (const float*)d_in[23];
    const float* c2b    = (const float*)d_in[24];
    const float* c3W    = (const float*)d_in[25];
    const float* c3b    = (const float*)d_in[26];
    float* out = (float*)d_out;

    float *p_h, *p_hn, *p_up, *p_agg, *p_Pd, *p_Ps, *p_zero;
    int *p_cnt;
    char *p_img;
    cudaGetSymbolAddress((void**)&p_h,    g_h);
    cudaGetSymbolAddress((void**)&p_hn,   g_hn);
    cudaGetSymbolAddress((void**)&p_up,   g_up);
    cudaGetSymbolAddress((void**)&p_agg,  g_agg);
    cudaGetSymbolAddress((void**)&p_Pd,   g_Pd);
    cudaGetSymbolAddress((void**)&p_Ps,   g_Ps);
    cudaGetSymbolAddress((void**)&p_zero, g_zero);
    cudaGetSymbolAddress((void**)&p_cnt,  g_cnt);
    cudaGetSymbolAddress((void**)&p_img,  g_Bimg);

    cudaFuncSetAttribute(gemm_mma<0,EPI_STORE>,      cudaFuncAttributeMaxDynamicSharedMemorySize, SMEM_BYTES);
    cudaFuncSetAttribute(gemm_mma<0,EPI_RESID>,      cudaFuncAttributeMaxDynamicSharedMemorySize, SMEM_BYTES);
    cudaFuncSetAttribute(gemm_mma<1,EPI_SCATTER>,    cudaFuncAttributeMaxDynamicSharedMemorySize, SMEM_BYTES);
    cudaFuncSetAttribute(gemm_mma<2,EPI_RELU_STORE>, cudaFuncAttributeMaxDynamicSharedMemorySize, SMEM_BYTES);

    const int GN  = (NN + 127) / 128;
    const int GE  = (NE + 127) / 128;
    const int ELT = (NN*HH + 255) / 256;
    const int NB  = (NN + SBK - 1) / SBK;

    auto chunk = [&](int idx) -> char* { return p_img + (size_t)idx * 65536; };

    // ---- prep weight images ----
    k_prepB<<<(16384+255)/256,256>>>(emb_W2, 128, 1, chunk(0));
    for (int i = 0; i < LL; i++){
        const float* Wd = m1W + (size_t)i*260*128;
        k_prepB<<<(16384+255)/256,256>>>(Wd,            128, 1, chunk(1 + i*7 + 0));
        k_prepB<<<(16384+255)/256,256>>>(Wd + 128*128,  128, 1, chunk(1 + i*7 + 1));
        k_prepB<<<(16384+255)/256,256>>>(m2W + (size_t)i*128*128, 128, 1, chunk(1 + i*7 + 2));
        k_prepB<<<(3*16384+255)/256,256>>>(u1W + (size_t)i*257*128, 257, 3, chunk(1 + i*7 + 3));
        k_prepB<<<(16384+255)/256,256>>>(u2W + (size_t)i*128*128, 128, 1, chunk(1 + i*7 + 6));
    }

    // ---- preprocessing: var, degree, counting sort by dst ----
    k_node_pre<<<(NN+255)/256,256>>>(pos);
    k_zero_i<<<(NN+255)/256,256>>>(p_cnt, NN);
    k_hist<<<(NE+255)/256,256>>>(dst);
    k_scanA<<<NB,SBK>>>();
    k_scanB<<<1,128>>>(NB);
    k_scanC<<<(NN+255)/256,256>>>();
    k_scatter<<<(NE+255)/256,256>>>(u, pos, src, dst);

    auto bn = [&](const float* x, float* y, const float* g, const float* be, bool relu){
        k_bn_zero<<<1,128>>>();
        k_bn_stats<<<(NN+255)/256,128>>>(x);
        k_bn_fin<<<1,128>>>(g, be);
        if (relu) k_bn_apply<true ><<<(NN*HH/4+255)/256,256>>>(x, y);
        else      k_bn_apply<false><<<(NN*HH/4+255)/256,256>>>(x, y);
    };

    // ---- embedding ----
    k_h0<<<(NN*HH+255)/256,256>>>(u, pos, emb_W1, emb_b1);
    bn(p_hn, p_h, emb_g1, emb_be1, true);
    gemm_mma<0,EPI_STORE><<<GN,256,SMEM_BYTES>>>(p_h, chunk(0), emb_b2, p_hn, nullptr, NN, 128, 1);
    bn(p_hn, p_h, emb_g2, emb_be2, false);

    // ---- message-passing layers ----
    for (int i = 0; i < LL; i++){
        const float* Wt = m1W + (size_t)i*260*128 + 256*128;
        gemm_mma<0,EPI_STORE><<<GN,256,SMEM_BYTES>>>(p_h, chunk(1+i*7+0), m1b + i*128, p_Pd, nullptr, NN, 128, 1);
        gemm_mma<0,EPI_STORE><<<GN,256,SMEM_BYTES>>>(p_h, chunk(1+i*7+1), p_zero,      p_Ps, nullptr, NN, 128, 1);
        k_zero<<<ELT,256>>>(p_agg, NN*HH);
        gemm_mma<1,EPI_SCATTER><<<GE,256,SMEM_BYTES>>>(nullptr, chunk(1+i*7+2), m2b + i*128, p_agg, Wt, NE, 128, 1);
        gemm_mma<2,EPI_RELU_STORE><<<GN,256,SMEM_BYTES>>>(nullptr, chunk(1+i*7+3), u1b + i*128, p_up, nullptr, NN, 257, 3);
        gemm_mma<0,EPI_RESID><<<GN,256,SMEM_BYTES>>>(p_up, chunk(1+i*7+6), u2b + i*128, p_hn, nullptr, NN, 128, 1);
        bn(p_hn, p_h, bng + i*128, bnb + i*128, false);
    }

    // ---- CNN head ----
    k_cnn<<<(NN+63)/64,64>>>(c1W, c1b, c2W, c2b, c3W, c3b, out);
}

// round 6
// speedup vs baseline: 4.3718x; 1.0044x over previous
#include <cuda_runtime.h>
#include <cuda_bf16.h>
#include <cstdint>

#define NN 50000
#define NE 600000
#define HH 128
#define LL 6

typedef unsigned long long u64;
typedef unsigned int u32;

// ---------------- scratch (static device buffers; no allocation) ----------------
__device__ float g_hn [NN*HH];      // raw pre-BN node tensor "n"
__device__ float g_up [NN*HH];
__device__ float g_agg[NN*HH];
__device__ float g_Pd [NN*HH];
__device__ float g_Ps [NN*HH];
__device__ float4 g_tl[NE];
__device__ int   g_sdst[NE];
__device__ int   g_ssrc[NE];
__device__ int   g_cnt[NN];
__device__ int   g_woff[NN];
__device__ int   g_bsum[128];
__device__ float g_invdeg[NN];
__device__ float g_var[NN];
__device__ float g_sum[HH];
__device__ float g_sumsq[HH];
__device__ float g_ba[HH];          // current BN affine scale
__device__ float g_bc[HH];          // current BN affine shift
__device__ float g_zero[HH];        // stays zero
// B weight images: 43 chunks x 64KB (hi 32KB [n][k] bf16, then lo 32KB)
#define NCHUNK_TOT 43
__device__ char g_Bimg[(size_t)NCHUNK_TOT * 65536];

// ---------------- PTX helpers (baseline ISA only: ldmatrix + mma.sync) ----------------
__device__ __forceinline__ u32 smem_u32(const void* p){
    u32 a; asm("{ .reg .u64 t; cvta.to.shared.u64 t, %1; cvt.u32.u64 %0, t; }" : "=r"(a) : "l"(p));
    return a;
}
__device__ __forceinline__ void ldsm4(u32 &r0, u32 &r1, u32 &r2, u32 &r3, u32 addr){
    asm volatile("ldmatrix.sync.aligned.m8n8.x4.shared.b16 {%0,%1,%2,%3}, [%4];"
        : "=r"(r0), "=r"(r1), "=r"(r2), "=r"(r3) : "r"(addr));
}
__device__ __forceinline__ void mma16816(float4 &d, const u32* a, u32 b0, u32 b1){
    asm volatile("mma.sync.aligned.m16n8k16.row.col.f32.bf16.bf16.f32 "
        "{%0,%1,%2,%3}, {%4,%5,%6,%7}, {%8,%9}, {%0,%1,%2,%3};"
        : "+f"(d.x), "+f"(d.y), "+f"(d.z), "+f"(d.w)
        : "r"(a[0]), "r"(a[1]), "r"(a[2]), "r"(a[3]), "r"(b0), "r"(b1));
}

#define EPI_RELU_STORE  0
#define EPI_SCATTER     1
#define EPI_RESID_STATS 2
#define EPI_STORE       3
#define EPI_STORE_STATS 4

// dynamic smem layout (bytes)
#define A_HI 0
#define A_LO 10240
#define B_HI 20480
#define B_LO 55296
#define WT_OFF 90112
#define I0_OFF 92160
#define I1_OFF 92672
#define TL_OFF 93184
#define F0_OFF 95232
#define F1_OFF 95744
#define BA_OFF 96256
#define BC_OFF 96768
#define SMEM_BYTES 97280
// s_red (128x132 floats = 67584 B) overlays A+B after compute

// A-fragment assembly (8 consecutive k-values for one row)
// AMODE 0: dense raw rows x 128
// AMODE 1: edge fused: relu(Pd[dst] + Ps[src] + tail@Wt)            (K=128)
// AMODE 2: update: [affine(n) | agg*invdeg | var | 0-pad]           (K=257)
// AMODE 3: dense + column affine (+ optional relu)                  (K=128)
template<int AMODE, bool ARELU>
__device__ __forceinline__ void a_frag8(const float* __restrict__ A, int arow,
    int kglob, int i0, int i1, float4 tl, float invd, float var,
    const float* __restrict__ s_wt, const float* __restrict__ s_ba,
    const float* __restrict__ s_bc, float* v)
{
    if (AMODE == 0){
        float4 a0 = *(const float4*)&A[(size_t)arow*128 + kglob];
        float4 a1 = *(const float4*)&A[(size_t)arow*128 + kglob + 4];
        v[0]=a0.x; v[1]=a0.y; v[2]=a0.z; v[3]=a0.w;
        v[4]=a1.x; v[5]=a1.y; v[6]=a1.z; v[7]=a1.w;
    } else if (AMODE == 1){
        float4 p0 = *(const float4*)&g_Pd[(size_t)i0*HH + kglob];
        float4 p1 = *(const float4*)&g_Pd[(size_t)i0*HH + kglob + 4];
        float4 q0 = *(const float4*)&g_Ps[(size_t)i1*HH + kglob];
        float4 q1 = *(const float4*)&g_Ps[(size_t)i1*HH + kglob + 4];
        v[0]=p0.x+q0.x; v[1]=p0.y+q0.y; v[2]=p0.z+q0.z; v[3]=p0.w+q0.w;
        v[4]=p1.x+q1.x; v[5]=p1.y+q1.y; v[6]=p1.z+q1.z; v[7]=p1.w+q1.w;
        #pragma unroll
        for (int t = 0; t < 4; t++){
            float tv = (&tl.x)[t];
            const float* wr = &s_wt[t*HH + kglob];
            #pragma unroll
            for (int kk = 0; kk < 8; kk++) v[kk] += tv * wr[kk];
        }
        #pragma unroll
        for (int kk = 0; kk < 8; kk++) v[kk] = fmaxf(v[kk], 0.f);
    } else if (AMODE == 2){
        if (kglob < 128){
            float4 a0 = *(const float4*)&g_hn[(size_t)arow*HH + kglob];
            float4 a1 = *(const float4*)&g_hn[(size_t)arow*HH + kglob + 4];
            v[0]=a0.x; v[1]=a0.y; v[2]=a0.z; v[3]=a0.w;
            v[4]=a1.x; v[5]=a1.y; v[6]=a1.z; v[7]=a1.w;
            #pragma unroll
            for (int kk = 0; kk < 8; kk++)
                v[kk] = s_ba[kglob+kk]*v[kk] + s_bc[kglob+kk];
        } else if (kglob < 256){
            float4 a0 = *(const float4*)&g_agg[(size_t)arow*HH + (kglob-128)];
            float4 a1 = *(const float4*)&g_agg[(size_t)arow*HH + (kglob-128) + 4];
            v[0]=a0.x*invd; v[1]=a0.y*invd; v[2]=a0.z*invd; v[3]=a0.w*invd;
            v[4]=a1.x*invd; v[5]=a1.y*invd; v[6]=a1.z*invd; v[7]=a1.w*invd;
        } else {
            #pragma unroll
            for (int kk = 0; kk < 8; kk++) v[kk] = 0.f;
            if (kglob == 256) v[0] = var;
        }
    } else { // AMODE 3
        float4 a0 = *(const float4*)&A[(size_t)arow*128 + kglob];
        float4 a1 = *(const float4*)&A[(size_t)arow*128 + kglob + 4];
        v[0]=a0.x; v[1]=a0.y; v[2]=a0.z; v[3]=a0.w;
        v[4]=a1.x; v[5]=a1.y; v[6]=a1.z; v[7]=a1.w;
        #pragma unroll
        for (int kk = 0; kk < 8; kk++){
            v[kk] = s_ba[kglob+kk]*v[kk] + s_bc[kglob+kk];
            if (ARELU) v[kk] = fmaxf(v[kk], 0.f);
        }
    }
}

// ---------------- tensor-core GEMM via mma.sync: 128x128 tile per CTA ----------------
template<int AMODE, int EPI, bool ARELU>
__global__ __launch_bounds__(256, 2)
void gemm_mma(const float* __restrict__ A, const char* __restrict__ Bimg,
              const float* __restrict__ bias, float* __restrict__ out,
              const float* __restrict__ Wt, int rows, int K, int nchunks)
{
    extern __shared__ __align__(16) char smem[];
    const u32 sb  = smem_u32(smem);
    const int tid = threadIdx.x;
    const int wid = tid >> 5;
    const int lane = tid & 31;
    const int base = blockIdx.x * 128;

    int*    s_i0 = (int*)   (smem + I0_OFF);
    int*    s_i1 = (int*)   (smem + I1_OFF);
    float4* s_tl = (float4*)(smem + TL_OFF);
    float*  s_f0 = (float*) (smem + F0_OFF);
    float*  s_f1 = (float*) (smem + F1_OFF);
    float*  s_wt = (float*) (smem + WT_OFF);
    float*  s_ba = (float*) (smem + BA_OFF);
    float*  s_bc = (float*) (smem + BC_OFF);

    if (tid < 128){
        int r = base + tid;
        if (AMODE == 1){
            bool v = r < rows;
            s_i0[tid] = v ? g_sdst[r] : 0;
            s_i1[tid] = v ? g_ssrc[r] : 0;
            s_tl[tid] = v ? g_tl[r]   : make_float4(0.f,0.f,0.f,0.f);
        } else if (AMODE == 2){
            int rc = min(r, rows - 1);
            s_f0[tid] = g_invdeg[rc];
            s_f1[tid] = g_var[rc];
        }
        if (AMODE == 2 || AMODE == 3 || EPI == EPI_RESID_STATS){
            s_ba[tid] = g_ba[tid];
            s_bc[tid] = g_bc[tid];
        }
    }
    if (AMODE == 1){
        for (int i = tid; i < 4*HH; i += 256) s_wt[i] = Wt[i];
    }
    __syncthreads();

    const int warp_m = wid & 3;          // 4 warps over M
    const int warp_n = wid >> 2;         // 2 warps over N
    const int qi = lane & 7, qd = lane >> 3;

    const u32 aab = sb + A_HI + (u32)((warp_m*32 + (qd&1)*8 + qi)*80 + (qd>>1)*16);
    const u32 bab = sb + B_HI + (u32)((warp_n*64 + (qd>>1)*8 + qi)*272 + (qd&1)*16);

    float4 acc[2][8];
    #pragma unroll
    for (int i=0;i<2;i++)
        #pragma unroll
        for (int j=0;j<8;j++) acc[i][j] = make_float4(0.f,0.f,0.f,0.f);

    for (int sc = 0; sc < nchunks; sc++){
        __syncthreads();
        const uint4* bsrc = (const uint4*)(Bimg + (size_t)sc * 65536);
        #pragma unroll 4
        for (int i = tid; i < 2048; i += 256){
            int row = i >> 4, c = i & 15;
            *(uint4*)(smem + B_HI + row*272 + c*16) = bsrc[i];
            *(uint4*)(smem + B_LO + row*272 + c*16) = bsrc[2048 + i];
        }
        const int nsub = min(4, (K - sc*128 + 31) >> 5);
        for (int sub = 0; sub < nsub; sub++){
            __syncthreads();
            #pragma unroll 1
            for (int g = tid; g < 512; g += 256){
                int row = g >> 2;
                int k0l = (g & 3) * 8;
                int kglob = sc*128 + sub*32 + k0l;
                int arow = min(base + row, rows - 1);
                float v[8];
                a_frag8<AMODE, ARELU>(A, arow, kglob,
                               AMODE==1 ? s_i0[row] : 0,
                               AMODE==1 ? s_i1[row] : 0,
                               AMODE==1 ? s_tl[row] : make_float4(0,0,0,0),
                               AMODE==2 ? s_f0[row] : 0.f,
                               AMODE==2 ? s_f1[row] : 0.f,
                               s_wt, s_ba, s_bc, v);
                u32 hw[4], lw[4];
                #pragma unroll
                for (int q = 0; q < 4; q++){
                    __nv_bfloat16 h0 = __float2bfloat16(v[2*q]);
                    __nv_bfloat16 h1 = __float2bfloat16(v[2*q+1]);
                    __nv_bfloat16 l0 = __float2bfloat16(v[2*q]   - __bfloat162float(h0));
                    __nv_bfloat16 l1 = __float2bfloat16(v[2*q+1] - __bfloat162float(h1));
                    hw[q] = (u32)__bfloat16_as_ushort(h0) | ((u32)__bfloat16_as_ushort(h1) << 16);
                    lw[q] = (u32)__bfloat16_as_ushort(l0) | ((u32)__bfloat16_as_ushort(l1) << 16);
                }
                u32 aoff = (u32)(row*80 + k0l*2);
                *(uint4*)(smem + A_HI + aoff) = make_uint4(hw[0],hw[1],hw[2],hw[3]);
                *(uint4*)(smem + A_LO + aoff) = make_uint4(lw[0],lw[1],lw[2],lw[3]);
            }
            __syncthreads();
            #pragma unroll
            for (int ka = 0; ka < 2; ka++){
                u32 ah[2][4], al[2][4];
                u32 ab = aab + ka*32;
                ldsm4(ah[0][0],ah[0][1],ah[0][2],ah[0][3], ab);
                ldsm4(ah[1][0],ah[1][1],ah[1][2],ah[1][3], ab + 1280);
                ldsm4(al[0][0],al[0][1],al[0][2],al[0][3], ab + 10240);
                ldsm4(al[1][0],al[1][1],al[1][2],al[1][3], ab + 11520);
                u32 bb0 = bab + (u32)((sub*32 + ka*16) * 2);
                #pragma unroll
                for (int p = 0; p < 4; p++){
                    u32 h0,h1,h2,h3, l0,l1,l2,l3;
                    ldsm4(h0,h1,h2,h3, bb0 + p*4352);
                    ldsm4(l0,l1,l2,l3, bb0 + p*4352 + 34816);
                    #pragma unroll
                    for (int am = 0; am < 2; am++){
                        mma16816(acc[am][2*p],   ah[am], h0, h1);
                        mma16816(acc[am][2*p],   al[am], h0, h1);
                        mma16816(acc[am][2*p],   ah[am], l0, l1);
                        mma16816(acc[am][2*p+1], ah[am], h2, h3);
                        mma16816(acc[am][2*p+1], al[am], h2, h3);
                        mma16816(acc[am][2*p+1], ah[am], l2, l3);
                    }
                }
            }
        }
    }

    // ---- dump accumulators to smem staging tile (overlays A/B) ----
    __syncthreads();
    float* s_red = (float*)smem;
    #pragma unroll
    for (int am = 0; am < 2; am++)
        #pragma unroll
        for (int na = 0; na < 8; na++){
            int m0 = warp_m*32 + am*16 + (lane >> 2);
            int n0 = warp_n*64 + na*8 + (lane & 3)*2;
            float4 c = acc[am][na];
            *(float2*)&s_red[m0*132 + n0]     = make_float2(c.x, c.y);
            *(float2*)&s_red[(m0+8)*132 + n0] = make_float2(c.z, c.w);
        }
    __syncthreads();

    // ---------------- epilogue ----------------
    if (EPI == EPI_SCATTER){
        for (int i = tid; i < 4096; i += 256){
            int row = i >> 5, c4 = (i & 31)*4;
            float4 v  = *(float4*)&s_red[row*132 + c4];
            float4 bb = *(const float4*)&bias[c4];
            v.x = fmaxf(v.x + bb.x, 0.f); v.y = fmaxf(v.y + bb.y, 0.f);
            v.z = fmaxf(v.z + bb.z, 0.f); v.w = fmaxf(v.w + bb.w, 0.f);
            *(float4*)&s_red[row*132 + c4] = v;
        }
        __shared__ int s_nh;
        __shared__ int s_hd[128];
        if (tid == 0) s_nh = 0;
        __syncthreads();
        if (tid < 128){
            int r = base + tid;
            if (r < rows){
                bool head = (tid == 0) || (s_i0[tid] != s_i0[tid-1]);
                if (head){ int p = atomicAdd(&s_nh, 1); s_hd[p] = tid; }
            }
        }
        __syncthreads();
        int nh = s_nh;
        for (int item = tid; item < nh*32; item += 256){
            int h = s_hd[item >> 5];
            int strip = (item & 31) * 4;
            int d = s_i0[h];
            float a0=0.f, a1=0.f, a2=0.f, a3=0.f;
            int rr = h;
            while (rr < 128 && (base + rr) < rows && s_i0[rr] == d){
                float* rp = &s_red[rr*132 + strip];
                a0 += rp[0]; a1 += rp[1]; a2 += rp[2]; a3 += rp[3];
                rr++;
            }
            atomicAdd(&out[(size_t)d*HH + strip + 0], a0);
            atomicAdd(&out[(size_t)d*HH + strip + 1], a1);
            atomicAdd(&out[(size_t)d*HH + strip + 2], a2);
            atomicAdd(&out[(size_t)d*HH + strip + 3], a3);
        }
    } else {
        const bool STATS = (EPI == EPI_RESID_STATS) || (EPI == EPI_STORE_STATS);
        for (int i = tid; i < 4096; i += 256){
            int row = i >> 5, c4 = (i & 31)*4;
            int r = base + row;
            if (r >= rows) continue;
            float4 v  = *(float4*)&s_red[row*132 + c4];
            float4 bb = *(const float4*)&bias[c4];
            v.x += bb.x; v.y += bb.y; v.z += bb.z; v.w += bb.w;
            if (EPI == EPI_RELU_STORE || EPI == EPI_RESID_STATS){
                v.x = fmaxf(v.x, 0.f); v.y = fmaxf(v.y, 0.f);
                v.z = fmaxf(v.z, 0.f); v.w = fmaxf(v.w, 0.f);
            }
            if (EPI == EPI_RESID_STATS){
                // add affine(n_prev); out buffer == g_hn (in-place safe: own rows only)
                float4 nv = *(const float4*)&out[(size_t)r*HH + c4];
                v.x += s_ba[c4+0]*nv.x + s_bc[c4+0];
                v.y += s_ba[c4+1]*nv.y + s_bc[c4+1];
                v.z += s_ba[c4+2]*nv.z + s_bc[c4+2];
                v.w += s_ba[c4+3]*nv.w + s_bc[c4+3];
            }
            *(float4*)&out[(size_t)r*HH + c4] = v;
            if (STATS) *(float4*)&s_red[row*132 + c4] = v;
        }
        if (STATS){
            __syncthreads();
            int nval = min(128, rows - base);
            if (tid < 128){
                float s = 0.f, s2 = 0.f;
                for (int rr = 0; rr < nval; rr++){
                    float v = s_red[rr*132 + tid];
                    s += v; s2 += v*v;
                }
                atomicAdd(&g_sum[tid], s);
                atomicAdd(&g_sumsq[tid], s2);
            }
        }
    }
}

// ---------------- weight image prep: [n][k] split-bf16 linear ----------------
__global__ void k_prepB(const float* __restrict__ W, int Krows, int nchunks,
                        char* __restrict__ img){
    int idx = blockIdx.x*blockDim.x + threadIdx.x;
    int total = nchunks * 16384;
    if (idx >= total) return;
    int c = idx >> 14;
    int rem = idx & 16383;
    int n = rem & 127;
    int kcol = rem >> 7;
    int k = c*128 + kcol;
    float w = (k < Krows) ? W[(size_t)k*128 + n] : 0.f;
    __nv_bfloat16 bh = __float2bfloat16(w);
    __nv_bfloat16 bl = __float2bfloat16(w - __bfloat162float(bh));
    char* cb = img + (size_t)c*65536;
    ((__nv_bfloat16*)cb)[n*128 + kcol]           = bh;
    ((__nv_bfloat16*)(cb + 32768))[n*128 + kcol] = bl;
}

// ---------------- small kernels ----------------
__global__ void k_zero(float* __restrict__ p, int n){
    int i = blockIdx.x*blockDim.x + threadIdx.x;
    if (i < n) p[i] = 0.f;
}
__global__ void k_zero_i(int* __restrict__ p, int n){
    int i = blockIdx.x*blockDim.x + threadIdx.x;
    if (i < n) p[i] = 0;
}
__global__ void k_node_pre(const float* __restrict__ pos){
    int n = blockIdx.x*blockDim.x + threadIdx.x;
    if (n < NN) g_var[n] = pos[n*3+0];
}
__global__ void k_hist(const int* __restrict__ dst){
    int e = blockIdx.x*blockDim.x + threadIdx.x;
    if (e < NE) atomicAdd(&g_cnt[dst[e]], 1);
}
#define SBK 512
__global__ __launch_bounds__(SBK)
void k_scanA(){
    __shared__ int sd[SBK];
    int b = blockIdx.x, t = threadIdx.x;
    int i = b*SBK + t;
    int c = (i < NN) ? g_cnt[i] : 0;
    sd[t] = c; __syncthreads();
    for (int off = 1; off < SBK; off <<= 1){
        int add = (t >= off) ? sd[t-off] : 0;
        __syncthreads();
        sd[t] += add;
        __syncthreads();
    }
    if (i < NN) g_woff[i] = sd[t] - c;
    if (t == SBK-1) g_bsum[b] = sd[t];
}
__global__ void k_scanB(int nb){
    __shared__ int s[128];
    int t = threadIdx.x;
    s[t] = (t < nb) ? g_bsum[t] : 0;
    __syncthreads();
    if (t == 0){
        int run = 0;
        for (int i = 0; i < nb; i++){ int c = s[i]; s[i] = run; run += c; }
    }
    __syncthreads();
    if (t < nb) g_bsum[t] = s[t];
}
__global__ void k_scanC(){
    int i = blockIdx.x*blockDim.x + threadIdx.x;
    if (i < NN){
        g_woff[i] += g_bsum[i / SBK];
        g_invdeg[i] = 1.f / fmaxf((float)g_cnt[i], 1.f);
    }
}
__global__ void k_scatter(const float* __restrict__ u, const float* __restrict__ pos,
                          const int* __restrict__ src, const int* __restrict__ dst){
    int e = blockIdx.x*blockDim.x + threadIdx.x;
    if (e < NE){
        int s = src[e], d = dst[e];
        int p = atomicAdd(&g_woff[d], 1);
        g_sdst[p] = d;
        g_ssrc[p] = s;
        g_tl[p] = make_float4(u[d]-u[s],
                              pos[d*3+1]-pos[s*3+1],
                              pos[d*3+2]-pos[s*3+2],
                              pos[d*3+0]);
    }
}
__global__ void k_h0(const float* __restrict__ u, const float* __restrict__ pos,
                     const float* __restrict__ W1, const float* __restrict__ b1){
    int idx = blockIdx.x*blockDim.x + threadIdx.x;
    if (idx < NN*HH){
        int n = idx >> 7, j = idx & 127;
        g_hn[idx] = u[n]       * W1[j]
                  + pos[n*3+1] * W1[128+j]
                  + pos[n*3+2] * W1[256+j]
                  + pos[n*3+0] * W1[384+j]
                  + b1[j];
    }
}
__global__ void k_bn_zero(){
    int t = threadIdx.x;
    if (t < HH){ g_sum[t]=0.f; g_sumsq[t]=0.f; }
}
__global__ void k_bn_stats(const float* __restrict__ x){
    int j = threadIdx.x;
    int r0 = blockIdx.x * 256;
    int rend = min(r0 + 256, NN);
    float s = 0.f, s2 = 0.f;
    for (int r = r0; r < rend; r++){
        float v = x[(size_t)r*HH + j];
        s += v; s2 += v*v;
    }
    atomicAdd(&g_sum[j], s);
    atomicAdd(&g_sumsq[j], s2);
}
// computes affine, then zeros the accumulators for the next stats pass
__global__ void k_bn_fin(const float* __restrict__ g, const float* __restrict__ be){
    int j = threadIdx.x;
    float mu  = g_sum[j]   * (1.f/NN);
    float var = g_sumsq[j] * (1.f/NN) - mu*mu;
    float a = g[j] * rsqrtf(var + 1e-5f);
    g_ba[j] = a;
    g_bc[j] = be[j] - a*mu;
    g_sum[j] = 0.f;
    g_sumsq[j] = 0.f;
}

// ---------------- CNN head (applies current affine to n on load) ----------------
__global__ __launch_bounds__(64)
void k_cnn(const float* __restrict__ c1W, const float* __restrict__ c1b,
           const float* __restrict__ c2W, const float* __restrict__ c2b,
           const float* __restrict__ c3W, const float* __restrict__ c3b,
           float* __restrict__ out){
    __shared__ float sx[64][129];
    __shared__ float w1[64], w2[384], w3[64], b1[4], b2[8], b3[1];
    int tid = threadIdx.x;
    int base = blockIdx.x * 64;

    w1[tid] = c1W[tid];
    w3[tid] = c3W[tid];
    for (int i = tid; i < 384; i += 64) w2[i] = c2W[i];
    if (tid < 4) b1[tid] = c1b[tid];
    if (tid < 8) b2[tid] = c2b[tid];
    if (tid == 0) b3[0] = c3b[0];

    float a0 = g_ba[tid],    c0 = g_bc[tid];
    float a1_ = g_ba[tid+64], c1_ = g_bc[tid+64];
    for (int r = 0; r < 64; r++){
        int row = base + r; int rr = row < NN ? row : NN-1;
        sx[r][tid]    = a0 * g_hn[(size_t)rr*HH + tid]      + c0;
        sx[r][tid+64] = a1_* g_hn[(size_t)rr*HH + tid + 64] + c1_;
    }
    __syncthreads();

    int node = base + tid;
    if (node >= NN) return;

    float o1[4][38];
    #pragma unroll
    for (int c = 0; c < 4; c++)
        for (int p = 0; p < 38; p++){
            float s = b1[c];
            #pragma unroll
            for (int k = 0; k < 16; k++) s += sx[tid][3*p+k] * w1[c*16+k];
            o1[c][p] = fmaxf(s, 0.f);
        }
    float o2[8][9];
    for (int o = 0; o < 8; o++)
        for (int q = 0; q < 9; q++){
            float s = b2[o];
            for (int c = 0; c < 4; c++)
                #pragma unroll
                for (int k = 0; k < 12; k++) s += o1[c][3*q+k] * w2[(o*4+c)*12+k];
            o2[o][q] = fmaxf(s, 0.f);
        }
    float s = b3[0];
    #pragma unroll
    for (int o = 0; o < 8; o++)
        #pragma unroll
        for (int k = 0; k < 8; k++) s += o2[o][k] * w3[o*8+k];

    out[node] = 0.001f * s;
}

// ---------------- launch ----------------
extern "C" void kernel_launch(void* const* d_in, const int* in_sizes, int n_in,
                              void* d_out, int out_size)
{
    const float* u      = (const float*)d_in[0];
    const float* pos    = (const float*)d_in[1];
    const int*   ei     = (const int*)  d_in[2];
    const int*   src    = ei;
    const int*   dst    = ei + NE;
    const float* emb_W1 = (const float*)d_in[3];
    const float* emb_b1 = (const float*)d_in[4];
    const float* emb_g1 = (const float*)d_in[5];
    const float* emb_be1= (const float*)d_in[6];
    const float* emb_W2 = (const float*)d_in[7];
    const float* emb_b2 = (const float*)d_in[8];
    const float* emb_g2 = (const float*)d_in[9];
    const float* emb_be2= (const float*)d_in[10];
    const float* m1W    = (const float*)d_in[11];
    const float* m1b    = (const float*)d_in[12];
    const float* m2W    = (const float*)d_in[13];
    const float* m2b    = (const float*)d_in[14];
    const float* u1W    = (const float*)d_in[15];
    const float* u1b    = (const float*)d_in[16];
    const float* u2W    = (const float*)d_in[17];
    const float* u2b    = (const float*)d_in[18];
    const float* bng    = (const float*)d_in[19];
    const float* bnb    = (const float*)d_in[20];
    const float* c1W    = (const float*)d_in[21];
    const float* c1b    = (const float*)d_in[22];
    const float* c2W    = (const float*)d_in[23];
    const float* c2b    = (const float*)d_in[24];
    const float* c3W    = (const float*)d_in[25];
    const float* c3b    = (const float*)d_in[26];
    float* out = (float*)d_out;

    float *p_hn, *p_up, *p_agg, *p_Pd, *p_Ps, *p_zero;
    int *p_cnt;
    char *p_img;
    cudaGetSymbolAddress((void**)&p_hn,   g_hn);
    cudaGetSymbolAddress((void**)&p_up,   g_up);
    cudaGetSymbolAddress((void**)&p_agg,  g_agg);
    cudaGetSymbolAddress((void**)&p_Pd,   g_Pd);
    cudaGetSymbolAddress((void**)&p_Ps,   g_Ps);
    cudaGetSymbolAddress((void**)&p_zero, g_zero);
    cudaGetSymbolAddress((void**)&p_cnt,  g_cnt);
    cudaGetSymbolAddress((void**)&p_img,  g_Bimg);

    cudaFuncSetAttribute(gemm_mma<3,EPI_STORE_STATS,true>,  cudaFuncAttributeMaxDynamicSharedMemorySize, SMEM_BYTES);
    cudaFuncSetAttribute(gemm_mma<3,EPI_STORE,false>,       cudaFuncAttributeMaxDynamicSharedMemorySize, SMEM_BYTES);
    cudaFuncSetAttribute(gemm_mma<1,EPI_SCATTER,false>,     cudaFuncAttributeMaxDynamicSharedMemorySize, SMEM_BYTES);
    cudaFuncSetAttribute(gemm_mma<2,EPI_RELU_STORE,false>,  cudaFuncAttributeMaxDynamicSharedMemorySize, SMEM_BYTES);
    cudaFuncSetAttribute(gemm_mma<0,EPI_RESID_STATS,false>, cudaFuncAttributeMaxDynamicSharedMemorySize, SMEM_BYTES);

    const int GN  = (NN + 127) / 128;
    const int GE  = (NE + 127) / 128;
    const int ELT = (NN*HH + 255) / 256;
    const int NB  = (NN + SBK - 1) / SBK;

    auto chunk = [&](int idx) -> char* { return p_img + (size_t)idx * 65536; };

    // ---- prep weight images ----
    k_prepB<<<(16384+255)/256,256>>>(emb_W2, 128, 1, chunk(0));
    for (int i = 0; i < LL; i++){
        const float* Wd = m1W + (size_t)i*260*128;
        k_prepB<<<(16384+255)/256,256>>>(Wd,            128, 1, chunk(1 + i*7 + 0));
        k_prepB<<<(16384+255)/256,256>>>(Wd + 128*128,  128, 1, chunk(1 + i*7 + 1));
        k_prepB<<<(16384+255)/256,256>>>(m2W + (size_t)i*128*128, 128, 1, chunk(1 + i*7 + 2));
        k_prepB<<<(3*16384+255)/256,256>>>(u1W + (size_t)i*257*128, 257, 3, chunk(1 + i*7 + 3));
        k_prepB<<<(16384+255)/256,256>>>(u2W + (size_t)i*128*128, 128, 1, chunk(1 + i*7 + 6));
    }

    // ---- preprocessing: var, degree, counting sort by dst ----
    k_node_pre<<<(NN+255)/256,256>>>(pos);
    k_zero_i<<<(NN+255)/256,256>>>(p_cnt, NN);
    k_hist<<<(NE+255)/256,256>>>(dst);
    k_scanA<<<NB,SBK>>>();
    k_scanB<<<1,128>>>(NB);
    k_scanC<<<(NN+255)/256,256>>>();
    k_scatter<<<(NE+255)/256,256>>>(u, pos, src, dst);

    // ---- embedding: h0 raw -> BN1 affine -> GEMM(A=relu(affine)) w/ stats -> BN2 affine
    k_h0<<<(NN*HH+255)/256,256>>>(u, pos, emb_W1, emb_b1);
    k_bn_zero<<<1,128>>>();
    k_bn_stats<<<(NN+255)/256,128>>>(p_hn);
    k_bn_fin<<<1,128>>>(emb_g1, emb_be1);
    gemm_mma<3,EPI_STORE_STATS,true><<<GN,256,SMEM_BYTES>>>(p_hn, chunk(0), emb_b2, p_hn, nullptr, NN, 128, 1);
    k_bn_fin<<<1,128>>>(emb_g2, emb_be2);

    // ---- message-passing layers ----
    for (int i = 0; i < LL; i++){
        const float* Wt = m1W + (size_t)i*260*128 + 256*128;
        gemm_mma<3,EPI_STORE,false><<<GN,256,SMEM_BYTES>>>(p_hn, chunk(1+i*7+0), m1b + i*128, p_Pd, nullptr, NN, 128, 1);
        gemm_mma<3,EPI_STORE,false><<<GN,256,SMEM_BYTES>>>(p_hn, chunk(1+i*7+1), p_zero,      p_Ps, nullptr, NN, 128, 1);
        k_zero<<<ELT,256>>>(p_agg, NN*HH);
        gemm_mma<1,EPI_SCATTER,false><<<GE,256,SMEM_BYTES>>>(nullptr, chunk(1+i*7+2), m2b + i*128, p_agg, Wt, NE, 128, 1);
        gemm_mma<2,EPI_RELU_STORE,false><<<GN,256,SMEM_BYTES>>>(nullptr, chunk(1+i*7+3), u1b + i*128, p_up, nullptr, NN, 257, 3);
        gemm_mma<0,EPI_RESID_STATS,false><<<GN,256,SMEM_BYTES>>>(p_up, chunk(1+i*7+6), u2b + i*128, p_hn, nullptr, NN, 128, 1);
        k_bn_fin<<<1,128>>>(bng + i*128, bnb + i*128);
    }

    // ---- CNN head ----
    k_cnn<<<(NN+63)/64,64>>>(c1W, c1b, c2W, c2b, c3W, c3b, out);
}

// round 7
// speedup vs baseline: 5.1390x; 1.1755x over previous
#include <cuda_runtime.h>
#include <cuda_fp16.h>
#include <cstdint>

#define NN 50000
#define NE 600000
#define HH 128
#define LL 6

typedef unsigned long long u64;
typedef unsigned int u32;

// ---------------- scratch (static device buffers; no allocation) ----------------
__device__ float g_hn [NN*HH];      // raw pre-BN node tensor "n"
__device__ float g_up [NN*HH];
__device__ float g_agg[NN*HH];
__device__ float g_Pd [NN*HH];
__device__ float g_Ps [NN*HH];
__device__ float4 g_tl[NE];
__device__ int   g_sdst[NE];
__device__ int   g_ssrc[NE];
__device__ int   g_cnt[NN];
__device__ int   g_woff[NN];
__device__ int   g_bsum[128];
__device__ float g_invdeg[NN];
__device__ float g_var[NN];
__device__ float g_sum[HH];
__device__ float g_sumsq[HH];
__device__ float g_ba[HH];          // current BN affine scale
__device__ float g_bc[HH];          // current BN affine shift
__device__ float g_zero[HH];        // stays zero
// B weight images: 43 chunks x 64KB stride (fp16 hi-limb [n][k], 32KB used)
#define NCHUNK_TOT 43
__device__ char g_Bimg[(size_t)NCHUNK_TOT * 65536];

// ---------------- PTX helpers (baseline ISA only: ldmatrix + mma.sync) ----------------
__device__ __forceinline__ u32 smem_u32(const void* p){
    u32 a; asm("{ .reg .u64 t; cvta.to.shared.u64 t, %1; cvt.u32.u64 %0, t; }" : "=r"(a) : "l"(p));
    return a;
}
__device__ __forceinline__ void ldsm4(u32 &r0, u32 &r1, u32 &r2, u32 &r3, u32 addr){
    asm volatile("ldmatrix.sync.aligned.m8n8.x4.shared.b16 {%0,%1,%2,%3}, [%4];"
        : "=r"(r0), "=r"(r1), "=r"(r2), "=r"(r3) : "r"(addr));
}
__device__ __forceinline__ void mma16816(float4 &d, const u32* a, u32 b0, u32 b1){
    asm volatile("mma.sync.aligned.m16n8k16.row.col.f32.f16.f16.f32 "
        "{%0,%1,%2,%3}, {%4,%5,%6,%7}, {%8,%9}, {%0,%1,%2,%3};"
        : "+f"(d.x), "+f"(d.y), "+f"(d.z), "+f"(d.w)
        : "r"(a[0]), "r"(a[1]), "r"(a[2]), "r"(a[3]), "r"(b0), "r"(b1));
}

#define EPI_RELU_STORE  0
#define EPI_SCATTER     1
#define EPI_RESID_STATS 2
#define EPI_STORE       3
#define EPI_STORE_STATS 4

// dynamic smem layout (bytes)
// A tiles: 128 rows x 40 halves (80B stride); B: 128 n-rows x 136 halves (272B)
#define A_HI   0
#define A_LO   10240
#define B_HI   20480
#define WT_OFF 55296
// s_red (128x132 floats = 67584 B) overlays [0, 67584) after compute
#define I0_OFF 67584
#define I1_OFF 68096
#define TL_OFF 68608
#define F0_OFF 70656
#define F1_OFF 71168
#define BA_OFF 71680
#define BC_OFF 72192
#define SMEM_BYTES 72704

// A-fragment assembly (8 consecutive k-values for one row)
// AMODE 0: dense raw rows x 128
// AMODE 1: edge fused: relu(Pd[dst] + Ps[src] + tail@Wt)            (K=128)
// AMODE 2: update: [affine(n) | agg*invdeg | var | 0-pad]           (K=257)
// AMODE 3: dense + column affine (+ optional relu)                  (K=128)
template<int AMODE, bool ARELU>
__device__ __forceinline__ void a_frag8(const float* __restrict__ A, int arow,
    int kglob, int i0, int i1, float4 tl, float invd, float var,
    const float* __restrict__ s_wt, const float* __restrict__ s_ba,
    const float* __restrict__ s_bc, float* v)
{
    if (AMODE == 0){
        float4 a0 = *(const float4*)&A[(size_t)arow*128 + kglob];
        float4 a1 = *(const float4*)&A[(size_t)arow*128 + kglob + 4];
        v[0]=a0.x; v[1]=a0.y; v[2]=a0.z; v[3]=a0.w;
        v[4]=a1.x; v[5]=a1.y; v[6]=a1.z; v[7]=a1.w;
    } else if (AMODE == 1){
        float4 p0 = *(const float4*)&g_Pd[(size_t)i0*HH + kglob];
        float4 p1 = *(const float4*)&g_Pd[(size_t)i0*HH + kglob + 4];
        float4 q0 = *(const float4*)&g_Ps[(size_t)i1*HH + kglob];
        float4 q1 = *(const float4*)&g_Ps[(size_t)i1*HH + kglob + 4];
        v[0]=p0.x+q0.x; v[1]=p0.y+q0.y; v[2]=p0.z+q0.z; v[3]=p0.w+q0.w;
        v[4]=p1.x+q1.x; v[5]=p1.y+q1.y; v[6]=p1.z+q1.z; v[7]=p1.w+q1.w;
        #pragma unroll
        for (int t = 0; t < 4; t++){
            float tv = (&tl.x)[t];
            const float* wr = &s_wt[t*HH + kglob];
            #pragma unroll
            for (int kk = 0; kk < 8; kk++) v[kk] += tv * wr[kk];
        }
        #pragma unroll
        for (int kk = 0; kk < 8; kk++) v[kk] = fmaxf(v[kk], 0.f);
    } else if (AMODE == 2){
        if (kglob < 128){
            float4 a0 = *(const float4*)&g_hn[(size_t)arow*HH + kglob];
            float4 a1 = *(const float4*)&g_hn[(size_t)arow*HH + kglob + 4];
            v[0]=a0.x; v[1]=a0.y; v[2]=a0.z; v[3]=a0.w;
            v[4]=a1.x; v[5]=a1.y; v[6]=a1.z; v[7]=a1.w;
            #pragma unroll
            for (int kk = 0; kk < 8; kk++)
                v[kk] = s_ba[kglob+kk]*v[kk] + s_bc[kglob+kk];
        } else if (kglob < 256){
            float4 a0 = *(const float4*)&g_agg[(size_t)arow*HH + (kglob-128)];
            float4 a1 = *(const float4*)&g_agg[(size_t)arow*HH + (kglob-128) + 4];
            v[0]=a0.x*invd; v[1]=a0.y*invd; v[2]=a0.z*invd; v[3]=a0.w*invd;
            v[4]=a1.x*invd; v[5]=a1.y*invd; v[6]=a1.z*invd; v[7]=a1.w*invd;
        } else {
            #pragma unroll
            for (int kk = 0; kk < 8; kk++) v[kk] = 0.f;
            if (kglob == 256) v[0] = var;
        }
    } else { // AMODE 3
        float4 a0 = *(const float4*)&A[(size_t)arow*128 + kglob];
        float4 a1 = *(const float4*)&A[(size_t)arow*128 + kglob + 4];
        v[0]=a0.x; v[1]=a0.y; v[2]=a0.z; v[3]=a0.w;
        v[4]=a1.x; v[5]=a1.y; v[6]=a1.z; v[7]=a1.w;
        #pragma unroll
        for (int kk = 0; kk < 8; kk++){
            v[kk] = s_ba[kglob+kk]*v[kk] + s_bc[kglob+kk];
            if (ARELU) v[kk] = fmaxf(v[kk], 0.f);
        }
    }
}

// ---------------- tensor-core GEMM via mma.sync: persistent 128x128 tiles ----------------
// fp16 2-term: D = ah*bh + al*bh  (A exact to 22 bits, B = fp16(W))
template<int AMODE, int EPI, bool ARELU>
__global__ __launch_bounds__(256, 2)
void gemm_mma(const float* __restrict__ A, const char* __restrict__ Bimg,
              const float* __restrict__ bias, float* __restrict__ out,
              const float* __restrict__ Wt, int rows, int K, int nchunks)
{
    extern __shared__ __align__(16) char smem[];
    const u32 sb  = smem_u32(smem);
    const int tid = threadIdx.x;
    const int wid = tid >> 5;
    const int lane = tid & 31;

    int*    s_i0 = (int*)   (smem + I0_OFF);
    int*    s_i1 = (int*)   (smem + I1_OFF);
    float4* s_tl = (float4*)(smem + TL_OFF);
    float*  s_f0 = (float*) (smem + F0_OFF);
    float*  s_f1 = (float*) (smem + F1_OFF);
    float*  s_wt = (float*) (smem + WT_OFF);
    float*  s_ba = (float*) (smem + BA_OFF);
    float*  s_bc = (float*) (smem + BC_OFF);
    __shared__ int s_nh;
    __shared__ int s_hd[128];

    const int warp_m = wid & 3;
    const int warp_n = wid >> 2;
    const int qi = lane & 7, qd = lane >> 3;
    const u32 aab = sb + A_HI + (u32)((warp_m*32 + (qd&1)*8 + qi)*80 + (qd>>1)*16);
    const u32 bab = sb + B_HI + (u32)((warp_n*64 + (qd>>1)*8 + qi)*272 + (qd&1)*16);

    for (int base = blockIdx.x * 128; base < rows; base += gridDim.x * 128){
        __syncthreads();   // previous tile fully done before overwriting meta / WT

        if (tid < 128){
            int r = base + tid;
            if (AMODE == 1){
                bool v = r < rows;
                s_i0[tid] = v ? g_sdst[r] : 0;
                s_i1[tid] = v ? g_ssrc[r] : 0;
                s_tl[tid] = v ? g_tl[r]   : make_float4(0.f,0.f,0.f,0.f);
            } else if (AMODE == 2){
                int rc = min(r, rows - 1);
                s_f0[tid] = g_invdeg[rc];
                s_f1[tid] = g_var[rc];
            }
            if (AMODE == 2 || AMODE == 3 || EPI == EPI_RESID_STATS){
                s_ba[tid] = g_ba[tid];
                s_bc[tid] = g_bc[tid];
            }
        }
        if (AMODE == 1){
            for (int i = tid; i < 4*HH; i += 256) s_wt[i] = Wt[i];
        }
        __syncthreads();

        float4 acc[2][8];
        #pragma unroll
        for (int i=0;i<2;i++)
            #pragma unroll
            for (int j=0;j<8;j++) acc[i][j] = make_float4(0.f,0.f,0.f,0.f);

        for (int sc = 0; sc < nchunks; sc++){
            __syncthreads();
            // ---- load B chunk (fp16 hi limb, 32KB) ----
            const uint4* bsrc = (const uint4*)(Bimg + (size_t)sc * 65536);
            #pragma unroll 4
            for (int i = tid; i < 2048; i += 256){
                int row = i >> 4, c = i & 15;
                *(uint4*)(smem + B_HI + row*272 + c*16) = bsrc[i];
            }
            const int nsub = min(4, (K - sc*128 + 31) >> 5);
            for (int sub = 0; sub < nsub; sub++){
                __syncthreads();
                // ---- assemble A 128x32 into split-fp16 smem ----
                #pragma unroll 1
                for (int g = tid; g < 512; g += 256){
                    int row = g >> 2;
                    int k0l = (g & 3) * 8;
                    int kglob = sc*128 + sub*32 + k0l;
                    int arow = min(base + row, rows - 1);
                    float v[8];
                    a_frag8<AMODE, ARELU>(A, arow, kglob,
                                   AMODE==1 ? s_i0[row] : 0,
                                   AMODE==1 ? s_i1[row] : 0,
                                   AMODE==1 ? s_tl[row] : make_float4(0,0,0,0),
                                   AMODE==2 ? s_f0[row] : 0.f,
                                   AMODE==2 ? s_f1[row] : 0.f,
                                   s_wt, s_ba, s_bc, v);
                    u32 hw[4], lw[4];
                    #pragma unroll
                    for (int q = 0; q < 4; q++){
                        __half h0 = __float2half_rn(v[2*q]);
                        __half h1 = __float2half_rn(v[2*q+1]);
                        __half l0 = __float2half_rn(v[2*q]   - __half2float(h0));
                        __half l1 = __float2half_rn(v[2*q+1] - __half2float(h1));
                        hw[q] = (u32)__half_as_ushort(h0) | ((u32)__half_as_ushort(h1) << 16);
                        lw[q] = (u32)__half_as_ushort(l0) | ((u32)__half_as_ushort(l1) << 16);
                    }
                    u32 aoff = (u32)(row*80 + k0l*2);
                    *(uint4*)(smem + A_HI + aoff) = make_uint4(hw[0],hw[1],hw[2],hw[3]);
                    *(uint4*)(smem + A_LO + aoff) = make_uint4(lw[0],lw[1],lw[2],lw[3]);
                }
                __syncthreads();
                // ---- compute 2 k-atoms (k16 each), 2-term ----
                #pragma unroll
                for (int ka = 0; ka < 2; ka++){
                    u32 ah[2][4], al[2][4];
                    u32 ab = aab + ka*32;
                    ldsm4(ah[0][0],ah[0][1],ah[0][2],ah[0][3], ab);
                    ldsm4(ah[1][0],ah[1][1],ah[1][2],ah[1][3], ab + 1280);
                    ldsm4(al[0][0],al[0][1],al[0][2],al[0][3], ab + 10240);
                    ldsm4(al[1][0],al[1][1],al[1][2],al[1][3], ab + 11520);
                    u32 bb0 = bab + (u32)((sub*32 + ka*16) * 2);
                    #pragma unroll
                    for (int p = 0; p < 4; p++){
                        u32 h0,h1,h2,h3;
                        ldsm4(h0,h1,h2,h3, bb0 + p*4352);
                        #pragma unroll
                        for (int am = 0; am < 2; am++){
                            mma16816(acc[am][2*p],   ah[am], h0, h1);
                            mma16816(acc[am][2*p],   al[am], h0, h1);
                            mma16816(acc[am][2*p+1], ah[am], h2, h3);
                            mma16816(acc[am][2*p+1], al[am], h2, h3);
                        }
                    }
                }
            }
        }

        // ---- dump accumulators to smem staging tile (overlays A/B) ----
        __syncthreads();
        float* s_red = (float*)smem;
        #pragma unroll
        for (int am = 0; am < 2; am++)
            #pragma unroll
            for (int na = 0; na < 8; na++){
                int m0 = warp_m*32 + am*16 + (lane >> 2);
                int n0 = warp_n*64 + na*8 + (lane & 3)*2;
                float4 c = acc[am][na];
                *(float2*)&s_red[m0*132 + n0]     = make_float2(c.x, c.y);
                *(float2*)&s_red[(m0+8)*132 + n0] = make_float2(c.z, c.w);
            }
        __syncthreads();

        // ---------------- epilogue ----------------
        if (EPI == EPI_SCATTER){
            for (int i = tid; i < 4096; i += 256){
                int row = i >> 5, c4 = (i & 31)*4;
                float4 v  = *(float4*)&s_red[row*132 + c4];
                float4 bb = *(const float4*)&bias[c4];
                v.x = fmaxf(v.x + bb.x, 0.f); v.y = fmaxf(v.y + bb.y, 0.f);
                v.z = fmaxf(v.z + bb.z, 0.f); v.w = fmaxf(v.w + bb.w, 0.f);
                *(float4*)&s_red[row*132 + c4] = v;
            }
            if (tid == 0) s_nh = 0;
            __syncthreads();
            if (tid < 128){
                int r = base + tid;
                if (r < rows){
                    bool head = (tid == 0) || (s_i0[tid] != s_i0[tid-1]);
                    if (head){ int p = atomicAdd(&s_nh, 1); s_hd[p] = tid; }
                }
            }
            __syncthreads();
            int nh = s_nh;
            for (int item = tid; item < nh*32; item += 256){
                int h = s_hd[item >> 5];
                int strip = (item & 31) * 4;
                int d = s_i0[h];
                float a0=0.f, a1=0.f, a2=0.f, a3=0.f;
                int rr = h;
                while (rr < 128 && (base + rr) < rows && s_i0[rr] == d){
                    float* rp = &s_red[rr*132 + strip];
                    a0 += rp[0]; a1 += rp[1]; a2 += rp[2]; a3 += rp[3];
                    rr++;
                }
                atomicAdd(&out[(size_t)d*HH + strip + 0], a0);
                atomicAdd(&out[(size_t)d*HH + strip + 1], a1);
                atomicAdd(&out[(size_t)d*HH + strip + 2], a2);
                atomicAdd(&out[(size_t)d*HH + strip + 3], a3);
            }
        } else {
            const bool STATS = (EPI == EPI_RESID_STATS) || (EPI == EPI_STORE_STATS);
            for (int i = tid; i < 4096; i += 256){
                int row = i >> 5, c4 = (i & 31)*4;
                int r = base + row;
                if (r >= rows) continue;
                float4 v  = *(float4*)&s_red[row*132 + c4];
                float4 bb = *(const float4*)&bias[c4];
                v.x += bb.x; v.y += bb.y; v.z += bb.z; v.w += bb.w;
                if (EPI == EPI_RELU_STORE || EPI == EPI_RESID_STATS){
                    v.x = fmaxf(v.x, 0.f); v.y = fmaxf(v.y, 0.f);
                    v.z = fmaxf(v.z, 0.f); v.w = fmaxf(v.w, 0.f);
                }
                if (EPI == EPI_RESID_STATS){
                    float4 nv = *(const float4*)&out[(size_t)r*HH + c4];
                    v.x += s_ba[c4+0]*nv.x + s_bc[c4+0];
                    v.y += s_ba[c4+1]*nv.y + s_bc[c4+1];
                    v.z += s_ba[c4+2]*nv.z + s_bc[c4+2];
                    v.w += s_ba[c4+3]*nv.w + s_bc[c4+3];
                }
                *(float4*)&out[(size_t)r*HH + c4] = v;
                if (STATS) *(float4*)&s_red[row*132 + c4] = v;
            }
            if (STATS){
                __syncthreads();
                int nval = min(128, rows - base);
                if (tid < 128){
                    float s = 0.f, s2 = 0.f;
                    for (int rr = 0; rr < nval; rr++){
                        float v = s_red[rr*132 + tid];
                        s += v; s2 += v*v;
                    }
                    atomicAdd(&g_sum[tid], s);
                    atomicAdd(&g_sumsq[tid], s2);
                }
            }
        }
    }
}

// ---------------- weight image prep: [n][k] fp16 hi limb, linear ----------------
__global__ void k_prepB(const float* __restrict__ W, int Krows, int nchunks,
                        char* __restrict__ img){
    int idx = blockIdx.x*blockDim.x + threadIdx.x;
    int total = nchunks * 16384;
    if (idx >= total) return;
    int c = idx >> 14;
    int rem = idx & 16383;
    int n = rem & 127;
    int kcol = rem >> 7;
    int k = c*128 + kcol;
    float w = (k < Krows) ? W[(size_t)k*128 + n] : 0.f;
    ((__half*)(img + (size_t)c*65536))[n*128 + kcol] = __float2half_rn(w);
}

// ---------------- small kernels ----------------
__global__ void k_zero(float* __restrict__ p, int n){
    int i = blockIdx.x*blockDim.x + threadIdx.x;
    if (i < n) p[i] = 0.f;
}
__global__ void k_zero_i(int* __restrict__ p, int n){
    int i = blockIdx.x*blockDim.x + threadIdx.x;
    if (i < n) p[i] = 0;
}
__global__ void k_node_pre(const float* __restrict__ pos){
    int n = blockIdx.x*blockDim.x + threadIdx.x;
    if (n < NN) g_var[n] = pos[n*3+0];
}
__global__ void k_hist(const int* __restrict__ dst){
    int e = blockIdx.x*blockDim.x + threadIdx.x;
    if (e < NE) atomicAdd(&g_cnt[dst[e]], 1);
}
#define SBK 512
__global__ __launch_bounds__(SBK)
void k_scanA(){
    __shared__ int sd[SBK];
    int b = blockIdx.x, t = threadIdx.x;
    int i = b*SBK + t;
    int c = (i < NN) ? g_cnt[i] : 0;
    sd[t] = c; __syncthreads();
    for (int off = 1; off < SBK; off <<= 1){
        int add = (t >= off) ? sd[t-off] : 0;
        __syncthreads();
        sd[t] += add;
        __syncthreads();
    }
    if (i < NN) g_woff[i] = sd[t] - c;
    if (t == SBK-1) g_bsum[b] = sd[t];
}
__global__ void k_scanB(int nb){
    __shared__ int s[128];
    int t = threadIdx.x;
    s[t] = (t < nb) ? g_bsum[t] : 0;
    __syncthreads();
    if (t == 0){
        int run = 0;
        for (int i = 0; i < nb; i++){ int c = s[i]; s[i] = run; run += c; }
    }
    __syncthreads();
    if (t < nb) g_bsum[t] = s[t];
}
__global__ void k_scanC(){
    int i = blockIdx.x*blockDim.x + threadIdx.x;
    if (i < NN){
        g_woff[i] += g_bsum[i / SBK];
        g_invdeg[i] = 1.f / fmaxf((float)g_cnt[i], 1.f);
    }
}
__global__ void k_scatter(const float* __restrict__ u, const float* __restrict__ pos,
                          const int* __restrict__ src, const int* __restrict__ dst){
    int e = blockIdx.x*blockDim.x + threadIdx.x;
    if (e < NE){
        int s = src[e], d = dst[e];
        int p = atomicAdd(&g_woff[d], 1);
        g_sdst[p] = d;
        g_ssrc[p] = s;
        g_tl[p] = make_float4(u[d]-u[s],
                              pos[d*3+1]-pos[s*3+1],
                              pos[d*3+2]-pos[s*3+2],
                              pos[d*3+0]);
    }
}
__global__ void k_h0(const float* __restrict__ u, const float* __restrict__ pos,
                     const float* __restrict__ W1, const float* __restrict__ b1){
    int idx = blockIdx.x*blockDim.x + threadIdx.x;
    if (idx < NN*HH){
        int n = idx >> 7, j = idx & 127;
        g_hn[idx] = u[n]       * W1[j]
                  + pos[n*3+1] * W1[128+j]
                  + pos[n*3+2] * W1[256+j]
                  + pos[n*3+0] * W1[384+j]
                  + b1[j];
    }
}
__global__ void k_bn_zero(){
    int t = threadIdx.x;
    if (t < HH){ g_sum[t]=0.f; g_sumsq[t]=0.f; }
}
__global__ void k_bn_stats(const float* __restrict__ x){
    int j = threadIdx.x;
    int r0 = blockIdx.x * 256;
    int rend = min(r0 + 256, NN);
    float s = 0.f, s2 = 0.f;
    for (int r = r0; r < rend; r++){
        float v = x[(size_t)r*HH + j];
        s += v; s2 += v*v;
    }
    atomicAdd(&g_sum[j], s);
    atomicAdd(&g_sumsq[j], s2);
}
__global__ void k_bn_fin(const float* __restrict__ g, const float* __restrict__ be){
    int j = threadIdx.x;
    float mu  = g_sum[j]   * (1.f/NN);
    float var = g_sumsq[j] * (1.f/NN) - mu*mu;
    float a = g[j] * rsqrtf(var + 1e-5f);
    g_ba[j] = a;
    g_bc[j] = be[j] - a*mu;
    g_sum[j] = 0.f;
    g_sumsq[j] = 0.f;
}

// ---------------- CNN head (applies current affine to n on load) ----------------
__global__ __launch_bounds__(64)
void k_cnn(const float* __restrict__ c1W, const float* __restrict__ c1b,
           const float* __restrict__ c2W, const float* __restrict__ c2b,
           const float* __restrict__ c3W, const float* __restrict__ c3b,
           float* __restrict__ out){
    __shared__ float sx[64][129];
    __shared__ float w1[64], w2[384], w3[64], b1[4], b2[8], b3[1];
    int tid = threadIdx.x;
    int base = blockIdx.x * 64;

    w1[tid] = c1W[tid];
    w3[tid] = c3W[tid];
    for (int i = tid; i < 384; i += 64) w2[i] = c2W[i];
    if (tid < 4) b1[tid] = c1b[tid];
    if (tid < 8) b2[tid] = c2b[tid];
    if (tid == 0) b3[0] = c3b[0];

    float a0 = g_ba[tid],    c0 = g_bc[tid];
    float a1_ = g_ba[tid+64], c1_ = g_bc[tid+64];
    for (int r = 0; r < 64; r++){
        int row = base + r; int rr = row < NN ? row : NN-1;
        sx[r][tid]    = a0 * g_hn[(size_t)rr*HH + tid]      + c0;
        sx[r][tid+64] = a1_* g_hn[(size_t)rr*HH + tid + 64] + c1_;
    }
    __syncthreads();

    int node = base + tid;
    if (node >= NN) return;

    float o1[4][38];
    #pragma unroll
    for (int c = 0; c < 4; c++)
        for (int p = 0; p < 38; p++){
            float s = b1[c];
            #pragma unroll
            for (int k = 0; k < 16; k++) s += sx[tid][3*p+k] * w1[c*16+k];
            o1[c][p] = fmaxf(s, 0.f);
        }
    float o2[8][9];
    for (int o = 0; o < 8; o++)
        for (int q = 0; q < 9; q++){
            float s = b2[o];
            for (int c = 0; c < 4; c++)
                #pragma unroll
                for (int k = 0; k < 12; k++) s += o1[c][3*q+k] * w2[(o*4+c)*12+k];
            o2[o][q] = fmaxf(s, 0.f);
        }
    float s = b3[0];
    #pragma unroll
    for (int o = 0; o < 8; o++)
        #pragma unroll
        for (int k = 0; k < 8; k++) s += o2[o][k] * w3[o*8+k];

    out[node] = 0.001f * s;
}

// ---------------- launch ----------------
extern "C" void kernel_launch(void* const* d_in, const int* in_sizes, int n_in,
                              void* d_out, int out_size)
{
    const float* u      = (const float*)d_in[0];
    const float* pos    = (const float*)d_in[1];
    const int*   ei     = (const int*)  d_in[2];
    const int*   src    = ei;
    const int*   dst    = ei + NE;
    const float* emb_W1 = (const float*)d_in[3];
    const float* emb_b1 = (const float*)d_in[4];
    const float* emb_g1 = (const float*)d_in[5];
    const float* emb_be1= (const float*)d_in[6];
    const float* emb_W2 = (const float*)d_in[7];
    const float* emb_b2 = (const float*)d_in[8];
    const float* emb_g2 = (const float*)d_in[9];
    const float* emb_be2= (const float*)d_in[10];
    const float* m1W    = (const float*)d_in[11];
    const float* m1b    = (const float*)d_in[12];
    const float* m2W    = (const float*)d_in[13];
    const float* m2b    = (const float*)d_in[14];
    const float* u1W    = (const float*)d_in[15];
    const float* u1b    = (const float*)d_in[16];
    const float* u2W    = (const float*)d_in[17];
    const float* u2b    = (const float*)d_in[18];
    const float* bng    = (const float*)d_in[19];
    const float* bnb    = (const float*)d_in[20];
    const float* c1W    = (const float*)d_in[21];
    const float* c1b    = (const float*)d_in[22];
    const float* c2W    = (const float*)d_in[23];
    const float* c2b    = (const float*)d_in[24];
    const float* c3W    = (const float*)d_in[25];
    const float* c3b    = (const float*)d_in[26];
    float* out = (float*)d_out;

    float *p_hn, *p_up, *p_agg, *p_Pd, *p_Ps, *p_zero;
    int *p_cnt;
    char *p_img;
    cudaGetSymbolAddress((void**)&p_hn,   g_hn);
    cudaGetSymbolAddress((void**)&p_up,   g_up);
    cudaGetSymbolAddress((void**)&p_agg,  g_agg);
    cudaGetSymbolAddress((void**)&p_Pd,   g_Pd);
    cudaGetSymbolAddress((void**)&p_Ps,   g_Ps);
    cudaGetSymbolAddress((void**)&p_zero, g_zero);
    cudaGetSymbolAddress((void**)&p_cnt,  g_cnt);
    cudaGetSymbolAddress((void**)&p_img,  g_Bimg);

    cudaFuncSetAttribute(gemm_mma<3,EPI_STORE_STATS,true>,  cudaFuncAttributeMaxDynamicSharedMemorySize, SMEM_BYTES);
    cudaFuncSetAttribute(gemm_mma<3,EPI_STORE,false>,       cudaFuncAttributeMaxDynamicSharedMemorySize, SMEM_BYTES);
    cudaFuncSetAttribute(gemm_mma<1,EPI_SCATTER,false>,     cudaFuncAttributeMaxDynamicSharedMemorySize, SMEM_BYTES);
    cudaFuncSetAttribute(gemm_mma<2,EPI_RELU_STORE,false>,  cudaFuncAttributeMaxDynamicSharedMemorySize, SMEM_BYTES);
    cudaFuncSetAttribute(gemm_mma<0,EPI_RESID_STATS,false>, cudaFuncAttributeMaxDynamicSharedMemorySize, SMEM_BYTES);

    const int GN_T = (NN + 127) / 128;        // node tiles
    const int GE_T = (NE + 127) / 128;        // edge tiles
    const int GN   = GN_T < 296 ? GN_T : 296; // persistent grids
    const int GE   = 296;
    const int ELT  = (NN*HH + 255) / 256;
    const int NB   = (NN + SBK - 1) / SBK;

    auto chunk = [&](int idx) -> char* { return p_img + (size_t)idx * 65536; };

    // ---- prep weight images ----
    k_prepB<<<(16384+255)/256,256>>>(emb_W2, 128, 1, chunk(0));
    for (int i = 0; i < LL; i++){
        const float* Wd = m1W + (size_t)i*260*128;
        k_prepB<<<(16384+255)/256,256>>>(Wd,            128, 1, chunk(1 + i*7 + 0));
        k_prepB<<<(16384+255)/256,256>>>(Wd + 128*128,  128, 1, chunk(1 + i*7 + 1));
        k_prepB<<<(16384+255)/256,256>>>(m2W + (size_t)i*128*128, 128, 1, chunk(1 + i*7 + 2));
        k_prepB<<<(3*16384+255)/256,256>>>(u1W + (size_t)i*257*128, 257, 3, chunk(1 + i*7 + 3));
        k_prepB<<<(16384+255)/256,256>>>(u2W + (size_t)i*128*128, 128, 1, chunk(1 + i*7 + 6));
    }

    // ---- preprocessing: var, degree, counting sort by dst ----
    k_node_pre<<<(NN+255)/256,256>>>(pos);
    k_zero_i<<<(NN+255)/256,256>>>(p_cnt, NN);
    k_hist<<<(NE+255)/256,256>>>(dst);
    k_scanA<<<NB,SBK>>>();
    k_scanB<<<1,128>>>(NB);
    k_scanC<<<(NN+255)/256,256>>>();
    k_scatter<<<(NE+255)/256,256>>>(u, pos, src, dst);

    // ---- embedding ----
    k_h0<<<(NN*HH+255)/256,256>>>(u, pos, emb_W1, emb_b1);
    k_bn_zero<<<1,128>>>();
    k_bn_stats<<<(NN+255)/256,128>>>(p_hn);
    k_bn_fin<<<1,128>>>(emb_g1, emb_be1);
    gemm_mma<3,EPI_STORE_STATS,true><<<GN,256,SMEM_BYTES>>>(p_hn, chunk(0), emb_b2, p_hn, nullptr, NN, 128, 1);
    k_bn_fin<<<1,128>>>(emb_g2, emb_be2);

    // ---- message-passing layers ----
    for (int i = 0; i < LL; i++){
        const float* Wt = m1W + (size_t)i*260*128 + 256*128;
        gemm_mma<3,EPI_STORE,false><<<GN,256,SMEM_BYTES>>>(p_hn, chunk(1+i*7+0), m1b + i*128, p_Pd, nullptr, NN, 128, 1);
        gemm_mma<3,EPI_STORE,false><<<GN,256,SMEM_BYTES>>>(p_hn, chunk(1+i*7+1), p_zero,      p_Ps, nullptr, NN, 128, 1);
        k_zero<<<ELT,256>>>(p_agg, NN*HH);
        gemm_mma<1,EPI_SCATTER,false><<<GE,256,SMEM_BYTES>>>(nullptr, chunk(1+i*7+2), m2b + i*128, p_agg, Wt, NE, 128, 1);
        gemm_mma<2,EPI_RELU_STORE,false><<<GN,256,SMEM_BYTES>>>(nullptr, chunk(1+i*7+3), u1b + i*128, p_up, nullptr, NN, 257, 3);
        gemm_mma<0,EPI_RESID_STATS,false><<<GN,256,SMEM_BYTES>>>(p_up, chunk(1+i*7+6), u2b + i*128, p_hn, nullptr, NN, 128, 1);
        k_bn_fin<<<1,128>>>(bng + i*128, bnb + i*128);
    }

    // ---- CNN head ----
    k_cnn<<<(NN+63)/64,64>>>(c1W, c1b, c2W, c2b, c3W, c3b, out);
}